// round 12
// baseline (speedup 1.0000x reference)
#include <cuda_runtime.h>
#include <cooperative_groups.h>
#include <math.h>

namespace cgx = cooperative_groups;
#define DEVINL __device__ __forceinline__

namespace {

constexpr int Bn   = 32;   // batch
constexpr int Tn   = 256;  // timesteps
constexpr int Nn   = 128;  // nodes
constexpr int DINn = 16;   // input features
constexpr int Un   = 64;   // hidden units
constexpr int Cn   = 4;    // classes
constexpr int CLS  = 4;    // cluster size (CTAs per batch)
constexpr int NP   = 32;   // nodes owned per CTA
constexpr int NT   = 1024; // threads per CTA (32 warps, occ 50%)

typedef unsigned long long ull;

// packed fp32x2 FMA (sm_103a): d.lo += a.lo*b.lo; d.hi += a.hi*b.hi (exact fp32)
DEVINL void fma2(ull& d, ull a, ull b) {
  asm("fma.rn.f32x2 %0, %1, %2, %0;" : "+l"(d) : "l"(a), "l"(b));
}
DEVINL ull dup2(float a) {
  ull r; asm("mov.b64 %0, {%1, %1};" : "=l"(r) : "f"(a)); return r;
}
DEVINL float2 lohi(ull v) {
  float2 r; asm("mov.b64 {%0, %1}, %2;" : "=f"(r.x), "=f"(r.y) : "l"(v)); return r;
}
DEVINL float rsum(ull v) { const float2 t = lohi(v); return t.x + t.y; }

// Activation buffers TRANSPOSED: t[c][n], 3-bit XOR swizzle on float4 granules.
struct Smem {
  float P[NP * Nn];     // own 32 rows of support           (16 KB)
  float P2[NP * Nn];    // own 32 rows of support^2         (16 KB)
  float tx[DINn * Nn];  // transposed input frame           ( 8 KB)
  float th0[Un * Nn];   // transposed hidden, layer 0       (32 KB)
  float th1[Un * Nn];   // transposed hidden, layer 1       (32 KB)
  float trh[Un * Nn];   // transposed r*h                   (32 KB)
  float t1[Nn * NP];    // P z,   own nodes [c][n local]    (16 KB)
  float t2[Nn * NP];    // 2P^2z - z, own [c][n local]      (16 KB)
  float ub[Un * NP];    // update gate [u][n local]         ( 8 KB)
};                      // 45056 floats = 180224 B

DEVINL int key8(int c) { return (c >> 2) & 7; }

// row base + swizzle key for concat channel c (x-part then h-part)
template <int CH0>
DEVINL const float* zrow(const float* __restrict__ s0t,
                         const float* __restrict__ s1t, int c, int& key) {
  if (c < CH0) { key = key8(c); return s0t + c * Nn; }
  const int ch = c - CH0;
  key = key8(ch);
  return s1t + ch * Nn;
}

// ---- gate hop1 (threads 0-511, 16 warps): t1[c][n] = sum_k P[n][k] z[k][c].
// warp = 4 nodes x 64 channels (lane = 2 ch), k-packed f32x2.
template <int CH0>
DEVINL void hop1g(Smem& S, int t, const float* __restrict__ s0t,
                  const float* __restrict__ s1t) {
  constexpr int CIN = CH0 + Un;
  const int w = t >> 5, lane = t & 31;
  const int c = (w >> 3) * 64 + lane * 2;  // chgrp = w>>3
  if (c >= CIN) return;
  const int n0 = (w & 7) * 4;
  const float* Pr0 = &S.P[(n0 + 0) * Nn];
  const float* Pr1 = &S.P[(n0 + 1) * Nn];
  const float* Pr2 = &S.P[(n0 + 2) * Nn];
  const float* Pr3 = &S.P[(n0 + 3) * Nn];
  int k0, k1;
  const float* zr0 = zrow<CH0>(s0t, s1t, c, k0);
  const float* zr1 = zrow<CH0>(s0t, s1t, c + 1, k1);  // k1 == k0 (same quad)
  ull a2[4][2] = {};
#pragma unroll 2
  for (int k = 0; k < Nn; k += 4) {
    const int g = k >> 2;
    const ulonglong2 za = *reinterpret_cast<const ulonglong2*>(zr0 + ((g ^ k0) << 2));
    const ulonglong2 zb = *reinterpret_cast<const ulonglong2*>(zr1 + ((g ^ k1) << 2));
    const ulonglong2 p0 = *reinterpret_cast<const ulonglong2*>(Pr0 + k);
    const ulonglong2 p1 = *reinterpret_cast<const ulonglong2*>(Pr1 + k);
    const ulonglong2 p2 = *reinterpret_cast<const ulonglong2*>(Pr2 + k);
    const ulonglong2 p3 = *reinterpret_cast<const ulonglong2*>(Pr3 + k);
    fma2(a2[0][0], p0.x, za.x); fma2(a2[0][0], p0.y, za.y);
    fma2(a2[1][0], p1.x, za.x); fma2(a2[1][0], p1.y, za.y);
    fma2(a2[2][0], p2.x, za.x); fma2(a2[2][0], p2.y, za.y);
    fma2(a2[3][0], p3.x, za.x); fma2(a2[3][0], p3.y, za.y);
    fma2(a2[0][1], p0.x, zb.x); fma2(a2[0][1], p0.y, zb.y);
    fma2(a2[1][1], p1.x, zb.x); fma2(a2[1][1], p1.y, zb.y);
    fma2(a2[2][1], p2.x, zb.x); fma2(a2[2][1], p2.y, zb.y);
    fma2(a2[3][1], p3.x, zb.x); fma2(a2[3][1], p3.y, zb.y);
  }
  const int gl = n0 >> 2;
  const int kd = key8(c);  // == key8(c+1)
  *reinterpret_cast<float4*>(&S.t1[c * NP + ((gl ^ kd) << 2)]) =
      make_float4(rsum(a2[0][0]), rsum(a2[1][0]), rsum(a2[2][0]), rsum(a2[3][0]));
  *reinterpret_cast<float4*>(&S.t1[(c + 1) * NP + ((gl ^ kd) << 2)]) =
      make_float4(rsum(a2[0][1]), rsum(a2[1][1]), rsum(a2[2][1]), rsum(a2[3][1]));
}

// ---- gate hop2 (threads 512-1023): t2[c][n] = 2*sum_k P2[n][k] z[k][c] - z[n][c].
template <int CH0>
DEVINL void hop2g(Smem& S, int t, int rank, const float* __restrict__ s0t,
                  const float* __restrict__ s1t) {
  constexpr int CIN = CH0 + Un;
  const int w = t >> 5, lane = t & 31;
  const int c = (w >> 3) * 64 + lane * 2;
  if (c >= CIN) return;
  const int n0 = (w & 7) * 4;
  const float* Pr0 = &S.P2[(n0 + 0) * Nn];
  const float* Pr1 = &S.P2[(n0 + 1) * Nn];
  const float* Pr2 = &S.P2[(n0 + 2) * Nn];
  const float* Pr3 = &S.P2[(n0 + 3) * Nn];
  int k0, k1;
  const float* zr0 = zrow<CH0>(s0t, s1t, c, k0);
  const float* zr1 = zrow<CH0>(s0t, s1t, c + 1, k1);
  ull a2[4][2] = {};
#pragma unroll 2
  for (int k = 0; k < Nn; k += 4) {
    const int g = k >> 2;
    const ulonglong2 za = *reinterpret_cast<const ulonglong2*>(zr0 + ((g ^ k0) << 2));
    const ulonglong2 zb = *reinterpret_cast<const ulonglong2*>(zr1 + ((g ^ k1) << 2));
    const ulonglong2 p0 = *reinterpret_cast<const ulonglong2*>(Pr0 + k);
    const ulonglong2 p1 = *reinterpret_cast<const ulonglong2*>(Pr1 + k);
    const ulonglong2 p2 = *reinterpret_cast<const ulonglong2*>(Pr2 + k);
    const ulonglong2 p3 = *reinterpret_cast<const ulonglong2*>(Pr3 + k);
    fma2(a2[0][0], p0.x, za.x); fma2(a2[0][0], p0.y, za.y);
    fma2(a2[1][0], p1.x, za.x); fma2(a2[1][0], p1.y, za.y);
    fma2(a2[2][0], p2.x, za.x); fma2(a2[2][0], p2.y, za.y);
    fma2(a2[3][0], p3.x, za.x); fma2(a2[3][0], p3.y, za.y);
    fma2(a2[0][1], p0.x, zb.x); fma2(a2[0][1], p0.y, zb.y);
    fma2(a2[1][1], p1.x, zb.x); fma2(a2[1][1], p1.y, zb.y);
    fma2(a2[2][1], p2.x, zb.x); fma2(a2[2][1], p2.y, zb.y);
    fma2(a2[3][1], p3.x, zb.x); fma2(a2[3][1], p3.y, zb.y);
  }
  const int gl = n0 >> 2;
  const int g0 = (rank * NP + n0) >> 2;
  const int kd = key8(c);
  const float4 z0a = *reinterpret_cast<const float4*>(zr0 + ((g0 ^ k0) << 2));
  const float4 z0b = *reinterpret_cast<const float4*>(zr1 + ((g0 ^ k1) << 2));
  *reinterpret_cast<float4*>(&S.t2[c * NP + ((gl ^ kd) << 2)]) =
      make_float4(2.f * rsum(a2[0][0]) - z0a.x, 2.f * rsum(a2[1][0]) - z0a.y,
                  2.f * rsum(a2[2][0]) - z0a.z, 2.f * rsum(a2[3][0]) - z0a.w);
  *reinterpret_cast<float4*>(&S.t2[(c + 1) * NP + ((gl ^ kd) << 2)]) =
      make_float4(2.f * rsum(a2[0][1]) - z0b.x, 2.f * rsum(a2[1][1]) - z0b.y,
                  2.f * rsum(a2[2][1]) - z0b.z, 2.f * rsum(a2[3][1]) - z0b.w);
}

// ---- candidate hop1 (threads 0-511, 16 warps): rh channels -> t1 rows
// [CH0, CH0+64). warp = 2 nodes x 64 ch (lane = 2 ch). x-rows persist.
template <int CH0>
DEVINL void hop1cd(Smem& S, int t) {
  const int w = t >> 5, lane = t & 31;
  const int c = lane * 2;
  const int n0 = w * 2;
  const float* Pr0 = &S.P[(n0 + 0) * Nn];
  const float* Pr1 = &S.P[(n0 + 1) * Nn];
  const int kk = (lane >> 1) & 7;  // key8(c) == key8(c+1)
  const float* zr0 = &S.trh[c * Nn];
  const float* zr1 = &S.trh[(c + 1) * Nn];
  ull a2[2][2] = {};
#pragma unroll 2
  for (int k = 0; k < Nn; k += 4) {
    const int g = (k >> 2) ^ kk;
    const ulonglong2 za = *reinterpret_cast<const ulonglong2*>(zr0 + (g << 2));
    const ulonglong2 zb = *reinterpret_cast<const ulonglong2*>(zr1 + (g << 2));
    const ulonglong2 p0 = *reinterpret_cast<const ulonglong2*>(Pr0 + k);
    const ulonglong2 p1 = *reinterpret_cast<const ulonglong2*>(Pr1 + k);
    fma2(a2[0][0], p0.x, za.x); fma2(a2[0][0], p0.y, za.y);
    fma2(a2[1][0], p1.x, za.x); fma2(a2[1][0], p1.y, za.y);
    fma2(a2[0][1], p0.x, zb.x); fma2(a2[0][1], p0.y, zb.y);
    fma2(a2[1][1], p1.x, zb.x); fma2(a2[1][1], p1.y, zb.y);
  }
  const int ksd = key8(CH0 + c);  // == key8(CH0+c+1)
  const int gl = n0 >> 2, ofl = n0 & 3;
  *reinterpret_cast<float2*>(&S.t1[(CH0 + c) * NP + ((gl ^ ksd) << 2) + ofl]) =
      make_float2(rsum(a2[0][0]), rsum(a2[1][0]));
  *reinterpret_cast<float2*>(&S.t1[(CH0 + c + 1) * NP + ((gl ^ ksd) << 2) + ofl]) =
      make_float2(rsum(a2[0][1]), rsum(a2[1][1]));
}

// ---- candidate hop2 (threads 512-1023): rh channels via P2 -> t2.
template <int CH0>
DEVINL void hop2cd(Smem& S, int t, int rank) {
  const int w = t >> 5, lane = t & 31;
  const int c = lane * 2;
  const int n0 = w * 2;
  const float* Pr0 = &S.P2[(n0 + 0) * Nn];
  const float* Pr1 = &S.P2[(n0 + 1) * Nn];
  const int kk = (lane >> 1) & 7;
  const float* zr0 = &S.trh[c * Nn];
  const float* zr1 = &S.trh[(c + 1) * Nn];
  ull a2[2][2] = {};
#pragma unroll 2
  for (int k = 0; k < Nn; k += 4) {
    const int g = (k >> 2) ^ kk;
    const ulonglong2 za = *reinterpret_cast<const ulonglong2*>(zr0 + (g << 2));
    const ulonglong2 zb = *reinterpret_cast<const ulonglong2*>(zr1 + (g << 2));
    const ulonglong2 p0 = *reinterpret_cast<const ulonglong2*>(Pr0 + k);
    const ulonglong2 p1 = *reinterpret_cast<const ulonglong2*>(Pr1 + k);
    fma2(a2[0][0], p0.x, za.x); fma2(a2[0][0], p0.y, za.y);
    fma2(a2[1][0], p1.x, za.x); fma2(a2[1][0], p1.y, za.y);
    fma2(a2[0][1], p0.x, zb.x); fma2(a2[0][1], p0.y, zb.y);
    fma2(a2[1][1], p1.x, zb.x); fma2(a2[1][1], p1.y, zb.y);
  }
  const int ksd = key8(CH0 + c);
  const int ng0 = rank * NP + n0;
  const int gw = ng0 >> 2, ofs = ng0 & 3;
  const int gl = n0 >> 2, ofl = n0 & 3;
  const float2 z0a = *reinterpret_cast<const float2*>(
      zr0 + ((gw ^ kk) << 2) + ofs);
  const float2 z0b = *reinterpret_cast<const float2*>(
      zr1 + ((gw ^ kk) << 2) + ofs);
  *reinterpret_cast<float2*>(&S.t2[(CH0 + c) * NP + ((gl ^ ksd) << 2) + ofl]) =
      make_float2(2.f * rsum(a2[0][0]) - z0a.x, 2.f * rsum(a2[1][0]) - z0a.y);
  *reinterpret_cast<float2*>(&S.t2[(CH0 + c + 1) * NP + ((gl ^ ksd) << 2) + ofl]) =
      make_float2(2.f * rsum(a2[0][1]) - z0b.x, 2.f * rsum(a2[1][1]) - z0b.y);
}

// ---- projection: NPT nodes per thread (4 gate, 2 cand), f32x2 node pairs.
template <int CH0, int COUT, int NPT>
DEVINL void accum(Smem& S, int tid, int rank, const float* __restrict__ W,
                  const float* __restrict__ s0t, const float* __restrict__ s1t,
                  ull* __restrict__ acc2) {
  constexpr int CIN = CH0 + Un;
  constexpr int LPO = NT / COUT;  // threads per output column
  const int oc = tid / LPO;
  const int n0 = (tid % LPO) * NPT;
  const int gl = n0 >> 2, ofl = n0 & 3;          // local granule (t1, t2)
  const int ng0 = rank * NP + n0;
  const int gg = ng0 >> 2, ofg = ng0 & 3;        // global granule (z0)
#pragma unroll 2
  for (int c = 0; c < CIN; ++c) {
    const ull w0 = dup2(W[(3 * c + 0) * COUT + oc]);
    const ull w1 = dup2(W[(3 * c + 1) * COUT + oc]);
    const ull w2 = dup2(W[(3 * c + 2) * COUT + oc]);
    const int k = key8(c);
    int zk;
    const float* zr = zrow<CH0>(s0t, s1t, c, zk);
    const float* t1r = &S.t1[c * NP];
    const float* t2r = &S.t2[c * NP];
    if (NPT == 4) {
      const ulonglong2 z0 = *reinterpret_cast<const ulonglong2*>(
          zr + ((gg ^ zk) << 2));
      const ulonglong2 z1 = *reinterpret_cast<const ulonglong2*>(
          t1r + ((gl ^ k) << 2));
      const ulonglong2 z2 = *reinterpret_cast<const ulonglong2*>(
          t2r + ((gl ^ k) << 2));
      fma2(acc2[0], z0.x, w0); fma2(acc2[0], z1.x, w1); fma2(acc2[0], z2.x, w2);
      fma2(acc2[1], z0.y, w0); fma2(acc2[1], z1.y, w1); fma2(acc2[1], z2.y, w2);
    } else {
      const ull z0 = *reinterpret_cast<const ull*>(zr + ((gg ^ zk) << 2) + ofg);
      const ull z1 = *reinterpret_cast<const ull*>(t1r + ((gl ^ k) << 2) + ofl);
      const ull z2 = *reinterpret_cast<const ull*>(t2r + ((gl ^ k) << 2) + ofl);
      fma2(acc2[0], z0, w0); fma2(acc2[0], z1, w1); fma2(acc2[0], z2, w2);
    }
  }
}

// ---- one DCGRU cell, cluster-cooperative; ht = this layer's transposed h.
template <int CH0>
DEVINL void cell(cgx::cluster_group& cl, Smem& S, Smem* const* Sp, int tid,
                 int rank, const float* __restrict__ s0t, float* __restrict__ ht,
                 const float* __restrict__ Wg, const float* __restrict__ bg,
                 const float* __restrict__ Wc, const float* __restrict__ bc) {
  const size_t hoff = (size_t)((const char*)ht - (const char*)&S);

  // ================= gate =================
  cl.sync();  // replicated inputs (h / trh / h-scatters) visible everywhere
  if (tid < 512) hop1g<CH0>(S, tid, s0t, ht);
  else           hop2g<CH0>(S, tid - 512, rank, s0t, ht);
  __syncthreads();
  {
    ull acc2[2] = {0ull, 0ull};
    accum<CH0, 128, 4>(S, tid, rank, Wg, s0t, ht, acc2);
    const int oc = tid >> 3;          // LPO = 8
    const int n0 = (tid & 7) * 4;
    const int ng0 = rank * NP + n0;
    const float bias = bg[oc];
    float v[4];
    {
      const float2 t0 = lohi(acc2[0]);
      const float2 t1v = lohi(acc2[1]);
      v[0] = 1.f / (1.f + __expf(-(t0.x + bias)));
      v[1] = 1.f / (1.f + __expf(-(t0.y + bias)));
      v[2] = 1.f / (1.f + __expf(-(t1v.x + bias)));
      v[3] = 1.f / (1.f + __expf(-(t1v.y + bias)));
    }
    if (oc < Un) {  // r-part -> trh (transposed), scattered to all ranks
      const int k = key8(oc);
      const int go = ((ng0 >> 2) ^ k) << 2;
      const float4 hh = *reinterpret_cast<const float4*>(ht + oc * Nn + go);
      const float4 rv = make_float4(v[0] * hh.x, v[1] * hh.y,
                                    v[2] * hh.z, v[3] * hh.w);
#pragma unroll
      for (int r = 0; r < CLS; ++r)
        *reinterpret_cast<float4*>(&Sp[r]->trh[oc * Nn + go]) = rv;
    } else {  // u-part -> local ub (transposed)
      const int ou = oc - Un;
      const int ku = key8(ou);
      *reinterpret_cast<float4*>(
          &S.ub[ou * NP + (((n0 >> 2) ^ ku) << 2)]) =
          make_float4(v[0], v[1], v[2], v[3]);
    }
  }

  // ================= candidate + update =================
  cl.sync();  // trh gathered everywhere; all ranks past gate accum
  if (tid < 512) hop1cd<CH0>(S, tid);
  else           hop2cd<CH0>(S, tid - 512, rank);
  __syncthreads();
  {
    ull acc2[1] = {0ull};
    accum<CH0, 64, 2>(S, tid, rank, Wc, s0t, S.trh, acc2);
    const int oc = tid >> 4;          // LPO = 16
    const int n0 = (tid & 15) * 2;
    const int ng0 = rank * NP + n0;
    const int k = key8(oc);
    const float bias = bc[oc];
    const float2 av = lohi(acc2[0]);
    const float2 uu = *reinterpret_cast<const float2*>(
        &S.ub[oc * NP + (((n0 >> 2) ^ k) << 2) + (n0 & 3)]);
    const int go = ((ng0 >> 2) ^ k) << 2;
    const int og = go + (ng0 & 3);
    const float2 hh = *reinterpret_cast<const float2*>(ht + oc * Nn + og);
    float2 hn;
    hn.x = uu.x * hh.x + (1.f - uu.x) * tanhf(av.x + bias);
    hn.y = uu.y * hh.y + (1.f - uu.y) * tanhf(av.y + bias);
#pragma unroll
    for (int r = 0; r < CLS; ++r) {
      float* hp = reinterpret_cast<float*>((char*)Sp[r] + hoff);
      *reinterpret_cast<float2*>(hp + oc * Nn + og) = hn;
    }
  }
}

}  // namespace

__global__ void __launch_bounds__(NT, 1) __cluster_dims__(CLS, 1, 1)
dcgru_kernel(
    const float* __restrict__ x_all,   // (B,T,N,DIN)
    const int* __restrict__ seq_len,   // (B)
    const float* __restrict__ support, // (N,N)
    const float* __restrict__ W0g, const float* __restrict__ b0g,
    const float* __restrict__ W0c, const float* __restrict__ b0c,
    const float* __restrict__ W1g, const float* __restrict__ b1g,
    const float* __restrict__ W1c, const float* __restrict__ b1c,
    const float* __restrict__ Wfc, const float* __restrict__ bfc,
    float* __restrict__ out) {         // (B,C)
  extern __shared__ float smraw[];
  Smem& S = *reinterpret_cast<Smem*>(smraw);
  cgx::cluster_group cl = cgx::this_cluster();
  const int rank = cl.block_rank();
  const int b = blockIdx.x / CLS;
  const int tid = threadIdx.x;

  Smem* Sp[CLS];
#pragma unroll
  for (int r = 0; r < CLS; ++r)
    Sp[r] = reinterpret_cast<Smem*>(cl.map_shared_rank(&S, r));

  // Load own 32 rows of support.
  for (int i = tid; i < NP * Nn; i += NT)
    S.P[i] = support[rank * NP * Nn + i];
  __syncthreads();

  // Precompute P2 = (own rows of) support^2. thread = (node, 4 k-values).
  {
    const int n = tid >> 5;
    const int k4 = (tid & 31) * 4;
    const float* Pr = &S.P[n * Nn];
    float acc[4] = {0.f, 0.f, 0.f, 0.f};
    for (int m = 0; m < Nn; ++m) {
      const float p = Pr[m];
      const float4 sv = *reinterpret_cast<const float4*>(
          support + (size_t)m * Nn + k4);
      acc[0] = fmaf(p, sv.x, acc[0]); acc[1] = fmaf(p, sv.y, acc[1]);
      acc[2] = fmaf(p, sv.z, acc[2]); acc[3] = fmaf(p, sv.w, acc[3]);
    }
    *reinterpret_cast<float4*>(&S.P2[n * Nn + k4]) =
        make_float4(acc[0], acc[1], acc[2], acc[3]);
  }

  // Zero transposed hidden states.
  for (int i = tid; i < Un * Nn; i += NT) {
    S.th0[i] = 0.f;
    S.th1[i] = 0.f;
  }

  const int tlast = seq_len[b] - 1;  // uniform across the cluster

  for (int t = 0; t <= tlast; ++t) {
    // stage current frame TRANSPOSED: tx[c][n] (swizzled); 512 float4 total
    if (tid < 512) {
      const float4 xv = reinterpret_cast<const float4*>(
          x_all + ((size_t)b * Tn + t) * (Nn * DINn))[tid];
      const int n = tid >> 2;
      const int c0 = (tid & 3) * 4;
      const int k = tid & 3;  // key8(c0+j) for all j<4
      const int base = ((n >> 2) ^ k) * 4 + (n & 3);
      S.tx[(c0 + 0) * Nn + base] = xv.x;
      S.tx[(c0 + 1) * Nn + base] = xv.y;
      S.tx[(c0 + 2) * Nn + base] = xv.z;
      S.tx[(c0 + 3) * Nn + base] = xv.w;
    }
    cell<DINn>(cl, S, Sp, tid, rank, S.tx, S.th0, W0g, b0g, W0c, b0c);
    cell<Un>(cl, S, Sp, tid, rank, S.th0, S.th1, W1g, b1g, W1c, b1c);
  }

  cl.sync();  // all th1 scatters visible in rank 0's copy

  if (rank == 0) {
    // classifier: max_n( relu(h1[n]) @ Wfc + bfc ); t1 is dead, use as scratch
    if (tid < 512) {
      const int n = tid >> 2;
      const int c = tid & 3;
      float a = 0.f;
#pragma unroll 8
      for (int u = 0; u < Un; ++u) {
        const float hv = S.th1[u * Nn + (((n >> 2) ^ key8(u)) << 2) + (n & 3)];
        a = fmaf(fmaxf(hv, 0.f), Wfc[u * Cn + c], a);
      }
      S.t1[n * Cn + c] = a + bfc[c];
    }
    __syncthreads();
    if (tid < Cn) {
      float m = S.t1[tid];
      for (int n2 = 1; n2 < Nn; ++n2) m = fmaxf(m, S.t1[n2 * Cn + tid]);
      out[b * Cn + tid] = m;
    }
  }
}

extern "C" void kernel_launch(void* const* d_in, const int* in_sizes, int n_in,
                              void* d_out, int out_size) {
  const float* x   = (const float*)d_in[0];
  const int*   sl  = (const int*)d_in[1];
  const float* sup = (const float*)d_in[2];
  const float* W0g = (const float*)d_in[3];
  const float* b0g = (const float*)d_in[4];
  const float* W0c = (const float*)d_in[5];
  const float* b0c = (const float*)d_in[6];
  const float* W1g = (const float*)d_in[7];
  const float* b1g = (const float*)d_in[8];
  const float* W1c = (const float*)d_in[9];
  const float* b1c = (const float*)d_in[10];
  const float* Wfc = (const float*)d_in[11];
  const float* bfc = (const float*)d_in[12];
  float* out = (float*)d_out;

  const size_t smem = sizeof(Smem);
  cudaFuncSetAttribute(dcgru_kernel,
                       cudaFuncAttributeMaxDynamicSharedMemorySize, (int)smem);
  dcgru_kernel<<<Bn * CLS, NT, smem>>>(x, sl, sup, W0g, b0g, W0c, b0c,
                                       W1g, b1g, W1c, b1c, Wfc, bfc, out);
}

// round 13
// speedup vs baseline: 1.1886x; 1.1886x over previous
#include <cuda_runtime.h>
#include <cooperative_groups.h>
#include <math.h>

namespace cgx = cooperative_groups;
#define DEVINL __device__ __forceinline__

namespace {

constexpr int Bn   = 32;   // batch
constexpr int Tn   = 256;  // timesteps
constexpr int Nn   = 128;  // nodes
constexpr int DINn = 16;   // input features
constexpr int Un   = 64;   // hidden units
constexpr int Cn   = 4;    // classes
constexpr int CLS  = 4;    // cluster size (CTAs per batch)
constexpr int NP   = 32;   // nodes owned per CTA
constexpr int NT   = 512;  // threads per CTA

typedef unsigned long long ull;

// packed fp32x2 FMA (sm_103a): d.lo += a.lo*b.lo; d.hi += a.hi*b.hi (exact fp32)
DEVINL void fma2(ull& d, ull a, ull b) {
  asm("fma.rn.f32x2 %0, %1, %2, %0;" : "+l"(d) : "l"(a), "l"(b));
}
DEVINL ull dup2(float a) {
  ull r; asm("mov.b64 %0, {%1, %1};" : "=l"(r) : "f"(a)); return r;
}
DEVINL float2 lohi(ull v) {
  float2 r; asm("mov.b64 {%0, %1}, %2;" : "=f"(r.x), "=f"(r.y) : "l"(v)); return r;
}
DEVINL float rsum(ull v) { const float2 t = lohi(v); return t.x + t.y; }

DEVINL unsigned sm2u32(const void* p) {
  unsigned a;
  asm("{ .reg .u64 t; cvta.to.shared.u64 t, %1; cvt.u32.u64 %0, t; }"
      : "=r"(a) : "l"(p));
  return a;
}

// Activation buffers TRANSPOSED: t[c][n], 3-bit XOR swizzle on float4 granules.
struct Smem {
  float P[NP * Nn];     // own 32 rows of support           (16 KB)
  float P2[NP * Nn];    // own 32 rows of support^2         (16 KB)
  float tx[DINn * Nn];  // transposed input frame           ( 8 KB)
  float th0[Un * Nn];   // transposed hidden, layer 0       (32 KB)
  float th1[Un * Nn];   // transposed hidden, layer 1       (32 KB)
  float trh[Un * Nn];   // transposed r*h                   (32 KB)
  float t1[Nn * NP];    // P z,   own nodes [c][n local]    (16 KB)
  float t2[Nn * NP];    // 2P^2z - z, own [c][n local]      (16 KB)
  float ub[Un * NP];    // update gate [u][n local]         ( 8 KB)
  ull cbar;             // cluster barrier mbarrier (8 B, 8-aligned)
};

DEVINL int key8(int c) { return (c >> 2) & 7; }

// ---- custom cluster barrier: no CCTL.IVALL (keeps L1D warm for W).
// __syncthreads drains this CTA's (D)SMEM stores; release-arrive on every
// rank's mbarrier; acquire-wait on the local one. Arrive count = CLS.
DEVINL void cbar_sync(Smem& S, Smem* const* Sp, int tid, int& phase) {
  __syncthreads();
  if (tid < CLS) {
    const unsigned ra = sm2u32(&Sp[tid]->cbar);
    asm volatile(
        "mbarrier.arrive.release.cluster.shared::cluster.b64 _, [%0];"
        :: "r"(ra) : "memory");
  }
  const unsigned la = sm2u32(&S.cbar);
  unsigned done;
  asm volatile(
      "{\n\t.reg .pred p;\n\t"
      "mbarrier.try_wait.parity.acquire.cluster.shared::cta.b64 p, [%1], %2;\n\t"
      "selp.b32 %0, 1, 0, p;\n\t}"
      : "=r"(done) : "r"(la), "r"((unsigned)phase) : "memory");
  if (!done) {
    asm volatile(
        "{\n\t.reg .pred P1;\n\t"
        "WL%=:\n\t"
        "mbarrier.try_wait.parity.acquire.cluster.shared::cta.b64 P1, [%0], %1, 0x989680;\n\t"
        "@P1 bra.uni WD%=;\n\t"
        "bra.uni WL%=;\n\t"
        "WD%=:\n\t}"
        :: "r"(la), "r"((unsigned)phase) : "memory");
  }
  phase ^= 1;
}

// row base + swizzle key for concat channel c (x-part then h-part)
template <int CH0>
DEVINL const float* zrow(const float* __restrict__ s0t,
                         const float* __restrict__ s1t, int c, int& key) {
  if (c < CH0) { key = key8(c); return s0t + c * Nn; }
  const int ch = c - CH0;
  key = key8(ch);
  return s1t + ch * Nn;
}

// ---- gate hop1 (threads 0-255): t1[c][n] = sum_k P[n][k] z[k][c], LOCAL.
template <int CH0>
DEVINL void hop1g(Smem& S, int t, const float* __restrict__ s0t,
                  const float* __restrict__ s1t) {
  constexpr int CIN = CH0 + Un;
  const int lane = t & 31;
  const int c4 = lane * 4;
  if (c4 >= CIN) return;
  const int n0 = (t >> 5) * 4;
  const float* Pr0 = &S.P[(n0 + 0) * Nn];
  const float* Pr1 = &S.P[(n0 + 1) * Nn];
  const float* Pr2 = &S.P[(n0 + 2) * Nn];
  const float* Pr3 = &S.P[(n0 + 3) * Nn];
  const float* zr[4];
  int zk[4];
#pragma unroll
  for (int j = 0; j < 4; ++j) zr[j] = zrow<CH0>(s0t, s1t, c4 + j, zk[j]);
  ull a2[4][4] = {};
#pragma unroll 2
  for (int k = 0; k < Nn; k += 4) {
    const int g = k >> 2;
    const ulonglong2 p0 = *reinterpret_cast<const ulonglong2*>(Pr0 + k);
    const ulonglong2 p1 = *reinterpret_cast<const ulonglong2*>(Pr1 + k);
    const ulonglong2 p2 = *reinterpret_cast<const ulonglong2*>(Pr2 + k);
    const ulonglong2 p3 = *reinterpret_cast<const ulonglong2*>(Pr3 + k);
#pragma unroll
    for (int j = 0; j < 4; ++j) {
      const ulonglong2 z = *reinterpret_cast<const ulonglong2*>(
          zr[j] + ((g ^ zk[j]) << 2));
      fma2(a2[0][j], p0.x, z.x); fma2(a2[0][j], p0.y, z.y);
      fma2(a2[1][j], p1.x, z.x); fma2(a2[1][j], p1.y, z.y);
      fma2(a2[2][j], p2.x, z.x); fma2(a2[2][j], p2.y, z.y);
      fma2(a2[3][j], p3.x, z.x); fma2(a2[3][j], p3.y, z.y);
    }
  }
  const int gl = n0 >> 2;
  const int tk = lane & 7;  // == key8(c4+j)
#pragma unroll
  for (int j = 0; j < 4; ++j)
    *reinterpret_cast<float4*>(&S.t1[(c4 + j) * NP + ((gl ^ tk) << 2)]) =
        make_float4(rsum(a2[0][j]), rsum(a2[1][j]),
                    rsum(a2[2][j]), rsum(a2[3][j]));
}

// ---- gate hop2 (threads 256-511): t2[c][n] = 2*sum_k P2[n][k] z[k][c] - z[n][c].
template <int CH0>
DEVINL void hop2g(Smem& S, int t, int rank, const float* __restrict__ s0t,
                  const float* __restrict__ s1t) {
  constexpr int CIN = CH0 + Un;
  const int lane = t & 31;
  const int c4 = lane * 4;
  if (c4 >= CIN) return;
  const int n0 = (t >> 5) * 4;
  const float* Pr0 = &S.P2[(n0 + 0) * Nn];
  const float* Pr1 = &S.P2[(n0 + 1) * Nn];
  const float* Pr2 = &S.P2[(n0 + 2) * Nn];
  const float* Pr3 = &S.P2[(n0 + 3) * Nn];
  const float* zr[4];
  int zk[4];
#pragma unroll
  for (int j = 0; j < 4; ++j) zr[j] = zrow<CH0>(s0t, s1t, c4 + j, zk[j]);
  ull a2[4][4] = {};
#pragma unroll 2
  for (int k = 0; k < Nn; k += 4) {
    const int g = k >> 2;
    const ulonglong2 p0 = *reinterpret_cast<const ulonglong2*>(Pr0 + k);
    const ulonglong2 p1 = *reinterpret_cast<const ulonglong2*>(Pr1 + k);
    const ulonglong2 p2 = *reinterpret_cast<const ulonglong2*>(Pr2 + k);
    const ulonglong2 p3 = *reinterpret_cast<const ulonglong2*>(Pr3 + k);
#pragma unroll
    for (int j = 0; j < 4; ++j) {
      const ulonglong2 z = *reinterpret_cast<const ulonglong2*>(
          zr[j] + ((g ^ zk[j]) << 2));
      fma2(a2[0][j], p0.x, z.x); fma2(a2[0][j], p0.y, z.y);
      fma2(a2[1][j], p1.x, z.x); fma2(a2[1][j], p1.y, z.y);
      fma2(a2[2][j], p2.x, z.x); fma2(a2[2][j], p2.y, z.y);
      fma2(a2[3][j], p3.x, z.x); fma2(a2[3][j], p3.y, z.y);
    }
  }
  const int gl = n0 >> 2;
  const int g0 = (rank * NP + n0) >> 2;
  const int tk = lane & 7;
#pragma unroll
  for (int j = 0; j < 4; ++j) {
    const float4 z0 = *reinterpret_cast<const float4*>(
        zr[j] + ((g0 ^ zk[j]) << 2));
    *reinterpret_cast<float4*>(&S.t2[(c4 + j) * NP + ((gl ^ tk) << 2)]) =
        make_float4(2.f * rsum(a2[0][j]) - z0.x, 2.f * rsum(a2[1][j]) - z0.y,
                    2.f * rsum(a2[2][j]) - z0.z, 2.f * rsum(a2[3][j]) - z0.w);
  }
}

// ---- candidate hop1 (threads 0-255): rh channels only -> t1 rows [CH0, CH0+64).
template <int CH0>
DEVINL void hop1cd(Smem& S, int t) {
  const int cn = t & 15;
  const int ch4 = cn * 4;
  const int tk = cn & 7;  // key8(ch4+j) in trh
  const int n0 = (t >> 4) * 2;
  const float* Pr0 = &S.P[(n0 + 0) * Nn];
  const float* Pr1 = &S.P[(n0 + 1) * Nn];
  const float* zr[4];
#pragma unroll
  for (int j = 0; j < 4; ++j) zr[j] = &S.trh[(ch4 + j) * Nn];
  ull a2[2][4] = {};
#pragma unroll 2
  for (int k = 0; k < Nn; k += 4) {
    const int g = (k >> 2) ^ tk;
    const ulonglong2 p0 = *reinterpret_cast<const ulonglong2*>(Pr0 + k);
    const ulonglong2 p1 = *reinterpret_cast<const ulonglong2*>(Pr1 + k);
#pragma unroll
    for (int j = 0; j < 4; ++j) {
      const ulonglong2 z = *reinterpret_cast<const ulonglong2*>(zr[j] + (g << 2));
      fma2(a2[0][j], p0.x, z.x); fma2(a2[0][j], p0.y, z.y);
      fma2(a2[1][j], p1.x, z.x); fma2(a2[1][j], p1.y, z.y);
    }
  }
  const int ksd = ((CH0 >> 2) + cn) & 7;  // key8 of destination row CH0+ch4+j
  const int gl = n0 >> 2, ofl = n0 & 3;
#pragma unroll
  for (int j = 0; j < 4; ++j)
    *reinterpret_cast<float2*>(
        &S.t1[(CH0 + ch4 + j) * NP + ((gl ^ ksd) << 2) + ofl]) =
        make_float2(rsum(a2[0][j]), rsum(a2[1][j]));
}

// ---- candidate hop2 (threads 256-511): rh channels via P2 -> t2.
template <int CH0>
DEVINL void hop2cd(Smem& S, int t, int rank) {
  const int cn = t & 15;
  const int ch4 = cn * 4;
  const int tk = cn & 7;
  const int n0 = (t >> 4) * 2;
  const float* Pr0 = &S.P2[(n0 + 0) * Nn];
  const float* Pr1 = &S.P2[(n0 + 1) * Nn];
  const float* zr[4];
#pragma unroll
  for (int j = 0; j < 4; ++j) zr[j] = &S.trh[(ch4 + j) * Nn];
  ull a2[2][4] = {};
#pragma unroll 2
  for (int k = 0; k < Nn; k += 4) {
    const int g = (k >> 2) ^ tk;
    const ulonglong2 p0 = *reinterpret_cast<const ulonglong2*>(Pr0 + k);
    const ulonglong2 p1 = *reinterpret_cast<const ulonglong2*>(Pr1 + k);
#pragma unroll
    for (int j = 0; j < 4; ++j) {
      const ulonglong2 z = *reinterpret_cast<const ulonglong2*>(zr[j] + (g << 2));
      fma2(a2[0][j], p0.x, z.x); fma2(a2[0][j], p0.y, z.y);
      fma2(a2[1][j], p1.x, z.x); fma2(a2[1][j], p1.y, z.y);
    }
  }
  const int ksd = ((CH0 >> 2) + cn) & 7;
  const int ng0 = rank * NP + n0;
  const int gw = ng0 >> 2, ofs = ng0 & 3;
  const int gl = n0 >> 2, ofl = n0 & 3;
#pragma unroll
  for (int j = 0; j < 4; ++j) {
    const float2 z0 = *reinterpret_cast<const float2*>(
        &S.trh[(ch4 + j) * Nn + ((gw ^ tk) << 2) + ofs]);
    *reinterpret_cast<float2*>(
        &S.t2[(CH0 + ch4 + j) * NP + ((gl ^ ksd) << 2) + ofl]) =
        make_float2(2.f * rsum(a2[0][j]) - z0.x, 2.f * rsum(a2[1][j]) - z0.y);
  }
}

// ---- projection: acc2[q] packs node pairs; t1/t2 local (stride NP).
template <int CH0, int COUT, int NPT>
DEVINL void accum(Smem& S, int tid, int rank, const float* __restrict__ W,
                  const float* __restrict__ s0t, const float* __restrict__ s1t,
                  ull* __restrict__ acc2) {
  constexpr int CIN = CH0 + Un;
  constexpr int LPO = NT / COUT;  // threads per output column
  const int oc = tid / LPO;
  const int n0 = (tid % LPO) * NPT;
  const int g1 = (rank * NP + n0) >> 2;  // global granule (replicated z0)
  const int g2 = n0 >> 2;                // local granule (t1, t2)
#pragma unroll 4
  for (int c = 0; c < CIN; ++c) {
    const ull w0 = dup2(W[(3 * c + 0) * COUT + oc]);
    const ull w1 = dup2(W[(3 * c + 1) * COUT + oc]);
    const ull w2 = dup2(W[(3 * c + 2) * COUT + oc]);
    const int k = key8(c);
    int zk;
    const float* zr = zrow<CH0>(s0t, s1t, c, zk);
    const float* t1r = &S.t1[c * NP];
    const float* t2r = &S.t2[c * NP];
#pragma unroll
    for (int q = 0; q < NPT / 4; ++q) {
      const ulonglong2 z0 = *reinterpret_cast<const ulonglong2*>(
          zr + (((g1 + q) ^ zk) << 2));
      const ulonglong2 z1 = *reinterpret_cast<const ulonglong2*>(
          t1r + (((g2 + q) ^ k) << 2));
      const ulonglong2 z2 = *reinterpret_cast<const ulonglong2*>(
          t2r + (((g2 + q) ^ k) << 2));
      fma2(acc2[2 * q + 0], z0.x, w0);
      fma2(acc2[2 * q + 0], z1.x, w1);
      fma2(acc2[2 * q + 0], z2.x, w2);
      fma2(acc2[2 * q + 1], z0.y, w0);
      fma2(acc2[2 * q + 1], z1.y, w1);
      fma2(acc2[2 * q + 1], z2.y, w2);
    }
  }
}

// ---- one DCGRU cell, cluster-cooperative; ht = this layer's transposed h.
template <int CH0>
DEVINL void cell(Smem& S, Smem* const* Sp, int tid, int rank, int& phase,
                 const float* __restrict__ s0t, float* __restrict__ ht,
                 const float* __restrict__ Wg, const float* __restrict__ bg,
                 const float* __restrict__ Wc, const float* __restrict__ bc) {
  const size_t hoff = (size_t)((const char*)ht - (const char*)&S);

  // ================= gate =================
  cbar_sync(S, Sp, tid, phase);  // replicated inputs visible everywhere
  if (tid < 256) hop1g<CH0>(S, tid, s0t, ht);
  else           hop2g<CH0>(S, tid - 256, rank, s0t, ht);
  __syncthreads();
  {
    ull acc2[4] = {0ull, 0ull, 0ull, 0ull};
    accum<CH0, 128, 8>(S, tid, rank, Wg, s0t, ht, acc2);
    float acc[8];
#pragma unroll
    for (int q = 0; q < 4; ++q) {
      const float2 t = lohi(acc2[q]);
      acc[2 * q] = t.x;
      acc[2 * q + 1] = t.y;
    }
    const int oc = tid >> 2;
    const int n0 = (tid & 3) * 8;
    const int ng0 = rank * NP + n0;
    const float bias = bg[oc];
    float v[8];
#pragma unroll
    for (int i = 0; i < 8; ++i)
      v[i] = 1.f / (1.f + __expf(-(acc[i] + bias)));
    if (oc < Un) {  // r-part -> trh (transposed), scattered to all ranks
      const int k = key8(oc);
      const int g = ng0 >> 2;
      const float* hr = ht + oc * Nn;
      const float4 h0 = *reinterpret_cast<const float4*>(hr + ((g ^ k) << 2));
      const float4 h1 = *reinterpret_cast<const float4*>(hr + (((g + 1) ^ k) << 2));
      const float4 r0 = make_float4(v[0] * h0.x, v[1] * h0.y, v[2] * h0.z, v[3] * h0.w);
      const float4 r1 = make_float4(v[4] * h1.x, v[5] * h1.y, v[6] * h1.z, v[7] * h1.w);
#pragma unroll
      for (int r = 0; r < CLS; ++r) {
        float* base = &Sp[r]->trh[oc * Nn];
        *reinterpret_cast<float4*>(base + ((g ^ k) << 2)) = r0;
        *reinterpret_cast<float4*>(base + (((g + 1) ^ k) << 2)) = r1;
      }
    } else {  // u-part -> local ub (transposed)
      const int ou = oc - Un;
      const int ku = key8(ou);
      const int gl = n0 >> 2;
      float* ur = &S.ub[ou * NP];
      *reinterpret_cast<float4*>(ur + ((gl ^ ku) << 2)) =
          make_float4(v[0], v[1], v[2], v[3]);
      *reinterpret_cast<float4*>(ur + (((gl + 1) ^ ku) << 2)) =
          make_float4(v[4], v[5], v[6], v[7]);
    }
  }

  // ================= candidate + update =================
  cbar_sync(S, Sp, tid, phase);  // trh gathered; all ranks past gate accum
  if (tid < 256) hop1cd<CH0>(S, tid);
  else           hop2cd<CH0>(S, tid - 256, rank);
  __syncthreads();
  {
    ull acc2[2] = {0ull, 0ull};
    accum<CH0, 64, 4>(S, tid, rank, Wc, s0t, S.trh, acc2);
    float acc[4];
    {
      float2 t = lohi(acc2[0]);
      acc[0] = t.x; acc[1] = t.y;
      t = lohi(acc2[1]);
      acc[2] = t.x; acc[3] = t.y;
    }
    const int oc = tid >> 3;
    const int n0 = (tid & 7) * 4;
    const int ng0 = rank * NP + n0;
    const int k = key8(oc);
    const float bias = bc[oc];
    const float4 uu = *reinterpret_cast<const float4*>(
        &S.ub[oc * NP] + (((n0 >> 2) ^ k) << 2));
    const int go = ((ng0 >> 2) ^ k) << 2;
    const float4 hh = *reinterpret_cast<const float4*>(ht + oc * Nn + go);
    float4 hn;
    hn.x = uu.x * hh.x + (1.f - uu.x) * tanhf(acc[0] + bias);
    hn.y = uu.y * hh.y + (1.f - uu.y) * tanhf(acc[1] + bias);
    hn.z = uu.z * hh.z + (1.f - uu.z) * tanhf(acc[2] + bias);
    hn.w = uu.w * hh.w + (1.f - uu.w) * tanhf(acc[3] + bias);
#pragma unroll
    for (int r = 0; r < CLS; ++r) {
      float* hp = reinterpret_cast<float*>((char*)Sp[r] + hoff);
      *reinterpret_cast<float4*>(hp + oc * Nn + go) = hn;
    }
  }
}

}  // namespace

__global__ void __launch_bounds__(NT, 1) __cluster_dims__(CLS, 1, 1)
dcgru_kernel(
    const float* __restrict__ x_all,   // (B,T,N,DIN)
    const int* __restrict__ seq_len,   // (B)
    const float* __restrict__ support, // (N,N)
    const float* __restrict__ W0g, const float* __restrict__ b0g,
    const float* __restrict__ W0c, const float* __restrict__ b0c,
    const float* __restrict__ W1g, const float* __restrict__ b1g,
    const float* __restrict__ W1c, const float* __restrict__ b1c,
    const float* __restrict__ Wfc, const float* __restrict__ bfc,
    float* __restrict__ out) {         // (B,C)
  extern __shared__ float smraw[];
  Smem& S = *reinterpret_cast<Smem*>(smraw);
  cgx::cluster_group cl = cgx::this_cluster();
  const int rank = cl.block_rank();
  const int b = blockIdx.x / CLS;
  const int tid = threadIdx.x;
  int phase = 0;

  Smem* Sp[CLS];
#pragma unroll
  for (int r = 0; r < CLS; ++r)
    Sp[r] = reinterpret_cast<Smem*>(cl.map_shared_rank(&S, r));

  // Load own 32 rows of support; init the cluster mbarrier.
  for (int i = tid; i < NP * Nn; i += NT)
    S.P[i] = support[rank * NP * Nn + i];
  if (tid == 0) {
    const unsigned la = sm2u32(&S.cbar);
    asm volatile("mbarrier.init.shared.b64 [%0], %1;"
                 :: "r"(la), "r"((unsigned)CLS) : "memory");
  }
  __syncthreads();

  // Precompute P2 = (own rows of) support^2. thread = (node, 8 k-values).
  {
    const int n = tid >> 4;
    const int k8 = (tid & 15) * 8;
    const float* Pr = &S.P[n * Nn];
    float acc[8] = {0.f, 0.f, 0.f, 0.f, 0.f, 0.f, 0.f, 0.f};
    for (int m = 0; m < Nn; ++m) {
      const float p = Pr[m];
      const float4 sa = *reinterpret_cast<const float4*>(
          support + (size_t)m * Nn + k8);
      const float4 sb = *reinterpret_cast<const float4*>(
          support + (size_t)m * Nn + k8 + 4);
      acc[0] = fmaf(p, sa.x, acc[0]); acc[1] = fmaf(p, sa.y, acc[1]);
      acc[2] = fmaf(p, sa.z, acc[2]); acc[3] = fmaf(p, sa.w, acc[3]);
      acc[4] = fmaf(p, sb.x, acc[4]); acc[5] = fmaf(p, sb.y, acc[5]);
      acc[6] = fmaf(p, sb.z, acc[6]); acc[7] = fmaf(p, sb.w, acc[7]);
    }
#pragma unroll
    for (int j = 0; j < 8; ++j) S.P2[n * Nn + k8 + j] = acc[j];
  }

  // Zero transposed hidden states.
  for (int i = tid; i < Un * Nn; i += NT) {
    S.th0[i] = 0.f;
    S.th1[i] = 0.f;
  }

  // One real cluster.sync: publishes mbarrier init across the cluster before
  // any rank's first arrive. (The only CCTL.IVALL in the whole kernel.)
  cl.sync();

  const int tlast = seq_len[b] - 1;  // uniform across the cluster

  for (int t = 0; t <= tlast; ++t) {
    // stage current frame TRANSPOSED: tx[c][n] (swizzled)
    const float4 xv = reinterpret_cast<const float4*>(
        x_all + ((size_t)b * Tn + t) * (Nn * DINn))[tid];
    {
      const int n = tid >> 2;
      const int c0 = (tid & 3) * 4;
      const int k = tid & 3;  // key8(c0+j) for all j<4
      const int base = ((n >> 2) ^ k) * 4 + (n & 3);
      S.tx[(c0 + 0) * Nn + base] = xv.x;
      S.tx[(c0 + 1) * Nn + base] = xv.y;
      S.tx[(c0 + 2) * Nn + base] = xv.z;
      S.tx[(c0 + 3) * Nn + base] = xv.w;
    }
    cell<DINn>(S, Sp, tid, rank, phase, S.tx, S.th0, W0g, b0g, W0c, b0c);
    cell<Un>(S, Sp, tid, rank, phase, S.th0, S.th1, W1g, b1g, W1c, b1c);
  }

  cbar_sync(S, Sp, tid, phase);  // all th1 scatters visible in rank 0's copy

  if (rank == 0) {
    // classifier: max_n( relu(h1[n]) @ Wfc + bfc ); t1 is dead, use as scratch
    const int n = tid >> 2;
    const int c = tid & 3;
    float a = 0.f;
#pragma unroll 8
    for (int u = 0; u < Un; ++u) {
      const float hv = S.th1[u * Nn + (((n >> 2) ^ key8(u)) << 2) + (n & 3)];
      a = fmaf(fmaxf(hv, 0.f), Wfc[u * Cn + c], a);
    }
    S.t1[n * Cn + c] = a + bfc[c];
    __syncthreads();
    if (tid < Cn) {
      float m = S.t1[tid];
      for (int n2 = 1; n2 < Nn; ++n2) m = fmaxf(m, S.t1[n2 * Cn + tid]);
      out[b * Cn + tid] = m;
    }
  }
}

extern "C" void kernel_launch(void* const* d_in, const int* in_sizes, int n_in,
                              void* d_out, int out_size) {
  const float* x   = (const float*)d_in[0];
  const int*   sl  = (const int*)d_in[1];
  const float* sup = (const float*)d_in[2];
  const float* W0g = (const float*)d_in[3];
  const float* b0g = (const float*)d_in[4];
  const float* W0c = (const float*)d_in[5];
  const float* b0c = (const float*)d_in[6];
  const float* W1g = (const float*)d_in[7];
  const float* b1g = (const float*)d_in[8];
  const float* W1c = (const float*)d_in[9];
  const float* b1c = (const float*)d_in[10];
  const float* Wfc = (const float*)d_in[11];
  const float* bfc = (const float*)d_in[12];
  float* out = (float*)d_out;

  const size_t smem = sizeof(Smem);
  cudaFuncSetAttribute(dcgru_kernel,
                       cudaFuncAttributeMaxDynamicSharedMemorySize, (int)smem);
  dcgru_kernel<<<Bn * CLS, NT, smem>>>(x, sl, sup, W0g, b0g, W0c, b0c,
                                       W1g, b1g, W1c, b1c, Wfc, bfc, out);
}

// round 14
// speedup vs baseline: 1.6077x; 1.3526x over previous
#include <cuda_runtime.h>
#include <cooperative_groups.h>
#include <math.h>

namespace cgx = cooperative_groups;
#define DEVINL __device__ __forceinline__

namespace {

constexpr int Bn   = 32;   // batch
constexpr int Tn   = 256;  // timesteps
constexpr int Nn   = 128;  // nodes
constexpr int DINn = 16;   // input features
constexpr int Un   = 64;   // hidden units
constexpr int Cn   = 4;    // classes
constexpr int CLS  = 4;    // cluster size (CTAs per batch)
constexpr int NP   = 32;   // nodes owned per CTA
constexpr int NT   = 512;  // threads per CTA

typedef unsigned long long ull;

// packed fp32x2 FMA (sm_103a): d.lo += a.lo*b.lo; d.hi += a.hi*b.hi (exact fp32)
DEVINL void fma2(ull& d, ull a, ull b) {
  asm("fma.rn.f32x2 %0, %1, %2, %0;" : "+l"(d) : "l"(a), "l"(b));
}
DEVINL ull dup2(float a) {
  ull r; asm("mov.b64 %0, {%1, %1};" : "=l"(r) : "f"(a)); return r;
}
DEVINL float2 lohi(ull v) {
  float2 r; asm("mov.b64 {%0, %1}, %2;" : "=f"(r.x), "=f"(r.y) : "l"(v)); return r;
}
DEVINL float rsum(ull v) { const float2 t = lohi(v); return t.x + t.y; }

// Activation buffers TRANSPOSED: t[c][n], 3-bit XOR swizzle on float4 granules.
struct Smem {
  float P[NP * Nn];     // own 32 rows of support           (16 KB)
  float P2[NP * Nn];    // own 32 rows of support^2         (16 KB)
  float tx[DINn * Nn];  // transposed input frame           ( 8 KB)
  float th0[Un * Nn];   // transposed hidden, layer 0       (32 KB)
  float th1[Un * Nn];   // transposed hidden, layer 1       (32 KB)
  float trh[Un * Nn];   // transposed r*h                   (32 KB)
  float t1[Nn * NP];    // P z,   own nodes [c][n local]    (16 KB)
  float t2[Nn * NP];    // 2P^2z - z, own [c][n local]      (16 KB)
  float ub[Un * NP];    // update gate [u][n local]         ( 8 KB)
};                      // 45056 floats = 180224 B

DEVINL int key8(int c) { return (c >> 2) & 7; }

// row base + swizzle key for concat channel c (x-part then h-part)
template <int CH0>
DEVINL const float* zrow(const float* __restrict__ s0t,
                         const float* __restrict__ s1t, int c, int& key) {
  if (c < CH0) { key = key8(c); return s0t + c * Nn; }
  const int ch = c - CH0;
  key = key8(ch);
  return s1t + ch * Nn;
}

// ---- gate hop1 (threads 0-255): t1[c][n] = sum_k P[n][k] z[k][c], LOCAL.
template <int CH0>
DEVINL void hop1g(Smem& S, int t, const float* __restrict__ s0t,
                  const float* __restrict__ s1t) {
  constexpr int CIN = CH0 + Un;
  const int lane = t & 31;
  const int c4 = lane * 4;
  if (c4 >= CIN) return;
  const int n0 = (t >> 5) * 4;
  const float* Pr0 = &S.P[(n0 + 0) * Nn];
  const float* Pr1 = &S.P[(n0 + 1) * Nn];
  const float* Pr2 = &S.P[(n0 + 2) * Nn];
  const float* Pr3 = &S.P[(n0 + 3) * Nn];
  const float* zr[4];
  int zk[4];
#pragma unroll
  for (int j = 0; j < 4; ++j) zr[j] = zrow<CH0>(s0t, s1t, c4 + j, zk[j]);
  ull a2[4][4] = {};
#pragma unroll 2
  for (int k = 0; k < Nn; k += 4) {
    const int g = k >> 2;
    const ulonglong2 p0 = *reinterpret_cast<const ulonglong2*>(Pr0 + k);
    const ulonglong2 p1 = *reinterpret_cast<const ulonglong2*>(Pr1 + k);
    const ulonglong2 p2 = *reinterpret_cast<const ulonglong2*>(Pr2 + k);
    const ulonglong2 p3 = *reinterpret_cast<const ulonglong2*>(Pr3 + k);
#pragma unroll
    for (int j = 0; j < 4; ++j) {
      const ulonglong2 z = *reinterpret_cast<const ulonglong2*>(
          zr[j] + ((g ^ zk[j]) << 2));
      fma2(a2[0][j], p0.x, z.x); fma2(a2[0][j], p0.y, z.y);
      fma2(a2[1][j], p1.x, z.x); fma2(a2[1][j], p1.y, z.y);
      fma2(a2[2][j], p2.x, z.x); fma2(a2[2][j], p2.y, z.y);
      fma2(a2[3][j], p3.x, z.x); fma2(a2[3][j], p3.y, z.y);
    }
  }
  const int gl = n0 >> 2;
  const int tk = lane & 7;  // == key8(c4+j)
#pragma unroll
  for (int j = 0; j < 4; ++j)
    *reinterpret_cast<float4*>(&S.t1[(c4 + j) * NP + ((gl ^ tk) << 2)]) =
        make_float4(rsum(a2[0][j]), rsum(a2[1][j]),
                    rsum(a2[2][j]), rsum(a2[3][j]));
}

// ---- gate hop2 (threads 256-511): t2[c][n] = 2*sum_k P2[n][k] z[k][c] - z[n][c].
template <int CH0>
DEVINL void hop2g(Smem& S, int t, int rank, const float* __restrict__ s0t,
                  const float* __restrict__ s1t) {
  constexpr int CIN = CH0 + Un;
  const int lane = t & 31;
  const int c4 = lane * 4;
  if (c4 >= CIN) return;
  const int n0 = (t >> 5) * 4;
  const float* Pr0 = &S.P2[(n0 + 0) * Nn];
  const float* Pr1 = &S.P2[(n0 + 1) * Nn];
  const float* Pr2 = &S.P2[(n0 + 2) * Nn];
  const float* Pr3 = &S.P2[(n0 + 3) * Nn];
  const float* zr[4];
  int zk[4];
#pragma unroll
  for (int j = 0; j < 4; ++j) zr[j] = zrow<CH0>(s0t, s1t, c4 + j, zk[j]);
  ull a2[4][4] = {};
#pragma unroll 2
  for (int k = 0; k < Nn; k += 4) {
    const int g = k >> 2;
    const ulonglong2 p0 = *reinterpret_cast<const ulonglong2*>(Pr0 + k);
    const ulonglong2 p1 = *reinterpret_cast<const ulonglong2*>(Pr1 + k);
    const ulonglong2 p2 = *reinterpret_cast<const ulonglong2*>(Pr2 + k);
    const ulonglong2 p3 = *reinterpret_cast<const ulonglong2*>(Pr3 + k);
#pragma unroll
    for (int j = 0; j < 4; ++j) {
      const ulonglong2 z = *reinterpret_cast<const ulonglong2*>(
          zr[j] + ((g ^ zk[j]) << 2));
      fma2(a2[0][j], p0.x, z.x); fma2(a2[0][j], p0.y, z.y);
      fma2(a2[1][j], p1.x, z.x); fma2(a2[1][j], p1.y, z.y);
      fma2(a2[2][j], p2.x, z.x); fma2(a2[2][j], p2.y, z.y);
      fma2(a2[3][j], p3.x, z.x); fma2(a2[3][j], p3.y, z.y);
    }
  }
  const int gl = n0 >> 2;
  const int g0 = (rank * NP + n0) >> 2;
  const int tk = lane & 7;
#pragma unroll
  for (int j = 0; j < 4; ++j) {
    const float4 z0 = *reinterpret_cast<const float4*>(
        zr[j] + ((g0 ^ zk[j]) << 2));
    *reinterpret_cast<float4*>(&S.t2[(c4 + j) * NP + ((gl ^ tk) << 2)]) =
        make_float4(2.f * rsum(a2[0][j]) - z0.x, 2.f * rsum(a2[1][j]) - z0.y,
                    2.f * rsum(a2[2][j]) - z0.z, 2.f * rsum(a2[3][j]) - z0.w);
  }
}

// ---- candidate hop1 (threads 0-255): rh channels only -> t1 rows [CH0, CH0+64).
template <int CH0>
DEVINL void hop1cd(Smem& S, int t) {
  const int cn = t & 15;
  const int ch4 = cn * 4;
  const int tk = cn & 7;  // key8(ch4+j) in trh
  const int n0 = (t >> 4) * 2;
  const float* Pr0 = &S.P[(n0 + 0) * Nn];
  const float* Pr1 = &S.P[(n0 + 1) * Nn];
  const float* zr[4];
#pragma unroll
  for (int j = 0; j < 4; ++j) zr[j] = &S.trh[(ch4 + j) * Nn];
  ull a2[2][4] = {};
#pragma unroll 2
  for (int k = 0; k < Nn; k += 4) {
    const int g = (k >> 2) ^ tk;
    const ulonglong2 p0 = *reinterpret_cast<const ulonglong2*>(Pr0 + k);
    const ulonglong2 p1 = *reinterpret_cast<const ulonglong2*>(Pr1 + k);
#pragma unroll
    for (int j = 0; j < 4; ++j) {
      const ulonglong2 z = *reinterpret_cast<const ulonglong2*>(zr[j] + (g << 2));
      fma2(a2[0][j], p0.x, z.x); fma2(a2[0][j], p0.y, z.y);
      fma2(a2[1][j], p1.x, z.x); fma2(a2[1][j], p1.y, z.y);
    }
  }
  const int ksd = ((CH0 >> 2) + cn) & 7;  // key8 of destination row CH0+ch4+j
  const int gl = n0 >> 2, ofl = n0 & 3;
#pragma unroll
  for (int j = 0; j < 4; ++j)
    *reinterpret_cast<float2*>(
        &S.t1[(CH0 + ch4 + j) * NP + ((gl ^ ksd) << 2) + ofl]) =
        make_float2(rsum(a2[0][j]), rsum(a2[1][j]));
}

// ---- candidate hop2 (threads 256-511): rh channels via P2 -> t2.
template <int CH0>
DEVINL void hop2cd(Smem& S, int t, int rank) {
  const int cn = t & 15;
  const int ch4 = cn * 4;
  const int tk = cn & 7;
  const int n0 = (t >> 4) * 2;
  const float* Pr0 = &S.P2[(n0 + 0) * Nn];
  const float* Pr1 = &S.P2[(n0 + 1) * Nn];
  const float* zr[4];
#pragma unroll
  for (int j = 0; j < 4; ++j) zr[j] = &S.trh[(ch4 + j) * Nn];
  ull a2[2][4] = {};
#pragma unroll 2
  for (int k = 0; k < Nn; k += 4) {
    const int g = (k >> 2) ^ tk;
    const ulonglong2 p0 = *reinterpret_cast<const ulonglong2*>(Pr0 + k);
    const ulonglong2 p1 = *reinterpret_cast<const ulonglong2*>(Pr1 + k);
#pragma unroll
    for (int j = 0; j < 4; ++j) {
      const ulonglong2 z = *reinterpret_cast<const ulonglong2*>(zr[j] + (g << 2));
      fma2(a2[0][j], p0.x, z.x); fma2(a2[0][j], p0.y, z.y);
      fma2(a2[1][j], p1.x, z.x); fma2(a2[1][j], p1.y, z.y);
    }
  }
  const int ksd = ((CH0 >> 2) + cn) & 7;
  const int ng0 = rank * NP + n0;
  const int gw = ng0 >> 2, ofs = ng0 & 3;
  const int gl = n0 >> 2, ofl = n0 & 3;
#pragma unroll
  for (int j = 0; j < 4; ++j) {
    const float2 z0 = *reinterpret_cast<const float2*>(
        &S.trh[(ch4 + j) * Nn + ((gw ^ tk) << 2) + ofs]);
    *reinterpret_cast<float2*>(
        &S.t2[(CH0 + ch4 + j) * NP + ((gl ^ ksd) << 2) + ofl]) =
        make_float2(2.f * rsum(a2[0][j]) - z0.x, 2.f * rsum(a2[1][j]) - z0.y);
  }
}

// ---- projection, REMAPPED: oc = tid & (COUT-1)  -> W LDG fully coalesced
// (32 consecutive words/warp); n-group = tid / COUT -> all z LDS warp-uniform
// broadcasts (1 wavefront each).
template <int CH0, int COUT, int NPT>
DEVINL void accum(Smem& S, int tid, int rank, const float* __restrict__ W,
                  const float* __restrict__ s0t, const float* __restrict__ s1t,
                  ull* __restrict__ acc2) {
  constexpr int CIN = CH0 + Un;
  const int oc = tid & (COUT - 1);
  const int n0 = (tid / COUT) * NPT;
  const int g1 = (rank * NP + n0) >> 2;  // global granule (replicated z0)
  const int g2 = n0 >> 2;                // local granule (t1, t2)
#pragma unroll 4
  for (int c = 0; c < CIN; ++c) {
    const ull w0 = dup2(W[(3 * c + 0) * COUT + oc]);
    const ull w1 = dup2(W[(3 * c + 1) * COUT + oc]);
    const ull w2 = dup2(W[(3 * c + 2) * COUT + oc]);
    const int k = key8(c);
    int zk;
    const float* zr = zrow<CH0>(s0t, s1t, c, zk);
    const float* t1r = &S.t1[c * NP];
    const float* t2r = &S.t2[c * NP];
#pragma unroll
    for (int q = 0; q < NPT / 4; ++q) {
      const ulonglong2 z0 = *reinterpret_cast<const ulonglong2*>(
          zr + (((g1 + q) ^ zk) << 2));
      const ulonglong2 z1 = *reinterpret_cast<const ulonglong2*>(
          t1r + (((g2 + q) ^ k) << 2));
      const ulonglong2 z2 = *reinterpret_cast<const ulonglong2*>(
          t2r + (((g2 + q) ^ k) << 2));
      fma2(acc2[2 * q + 0], z0.x, w0);
      fma2(acc2[2 * q + 0], z1.x, w1);
      fma2(acc2[2 * q + 0], z2.x, w2);
      fma2(acc2[2 * q + 1], z0.y, w0);
      fma2(acc2[2 * q + 1], z1.y, w1);
      fma2(acc2[2 * q + 1], z2.y, w2);
    }
  }
}

// ---- one DCGRU cell, cluster-cooperative; ht = this layer's transposed h.
template <int CH0>
DEVINL void cell(cgx::cluster_group& cl, Smem& S, Smem* const* Sp, int tid,
                 int rank, const float* __restrict__ s0t, float* __restrict__ ht,
                 const float* __restrict__ Wg, const float* __restrict__ bg,
                 const float* __restrict__ Wc, const float* __restrict__ bc) {
  const size_t hoff = (size_t)((const char*)ht - (const char*)&S);

  // ================= gate =================
  cl.sync();  // replicated inputs (h / trh / h-scatters) visible everywhere
  if (tid < 256) hop1g<CH0>(S, tid, s0t, ht);
  else           hop2g<CH0>(S, tid - 256, rank, s0t, ht);
  __syncthreads();
  {
    ull acc2[4] = {0ull, 0ull, 0ull, 0ull};
    accum<CH0, 128, 8>(S, tid, rank, Wg, s0t, ht, acc2);
    float acc[8];
#pragma unroll
    for (int q = 0; q < 4; ++q) {
      const float2 t = lohi(acc2[q]);
      acc[2 * q] = t.x;
      acc[2 * q + 1] = t.y;
    }
    const int oc = tid & 127;        // matches accum remap
    const int n0 = (tid >> 7) * 8;
    const int ng0 = rank * NP + n0;
    const float bias = bg[oc];
    float v[8];
#pragma unroll
    for (int i = 0; i < 8; ++i)
      v[i] = 1.f / (1.f + __expf(-(acc[i] + bias)));
    if (oc < Un) {  // r-part -> trh (transposed), scattered to all ranks
      const int k = key8(oc);
      const int g = ng0 >> 2;
      const float* hr = ht + oc * Nn;
      const float4 h0 = *reinterpret_cast<const float4*>(hr + ((g ^ k) << 2));
      const float4 h1 = *reinterpret_cast<const float4*>(hr + (((g + 1) ^ k) << 2));
      const float4 r0 = make_float4(v[0] * h0.x, v[1] * h0.y, v[2] * h0.z, v[3] * h0.w);
      const float4 r1 = make_float4(v[4] * h1.x, v[5] * h1.y, v[6] * h1.z, v[7] * h1.w);
#pragma unroll
      for (int r = 0; r < CLS; ++r) {
        float* base = &Sp[r]->trh[oc * Nn];
        *reinterpret_cast<float4*>(base + ((g ^ k) << 2)) = r0;
        *reinterpret_cast<float4*>(base + (((g + 1) ^ k) << 2)) = r1;
      }
    } else {  // u-part -> local ub (transposed)
      const int ou = oc - Un;
      const int ku = key8(ou);
      const int gl = n0 >> 2;
      float* ur = &S.ub[ou * NP];
      *reinterpret_cast<float4*>(ur + ((gl ^ ku) << 2)) =
          make_float4(v[0], v[1], v[2], v[3]);
      *reinterpret_cast<float4*>(ur + (((gl + 1) ^ ku) << 2)) =
          make_float4(v[4], v[5], v[6], v[7]);
    }
  }

  // ================= candidate + update =================
  cl.sync();  // trh gathered; all ranks past gate accum
  if (tid < 256) hop1cd<CH0>(S, tid);
  else           hop2cd<CH0>(S, tid - 256, rank);
  __syncthreads();
  {
    ull acc2[2] = {0ull, 0ull};
    accum<CH0, 64, 4>(S, tid, rank, Wc, s0t, S.trh, acc2);
    float acc[4];
    {
      float2 t = lohi(acc2[0]);
      acc[0] = t.x; acc[1] = t.y;
      t = lohi(acc2[1]);
      acc[2] = t.x; acc[3] = t.y;
    }
    const int oc = tid & 63;         // matches accum remap
    const int n0 = (tid >> 6) * 4;
    const int ng0 = rank * NP + n0;
    const int k = key8(oc);
    const float bias = bc[oc];
    const float4 uu = *reinterpret_cast<const float4*>(
        &S.ub[oc * NP] + (((n0 >> 2) ^ k) << 2));
    const int go = ((ng0 >> 2) ^ k) << 2;
    const float4 hh = *reinterpret_cast<const float4*>(ht + oc * Nn + go);
    float4 hn;
    hn.x = uu.x * hh.x + (1.f - uu.x) * tanhf(acc[0] + bias);
    hn.y = uu.y * hh.y + (1.f - uu.y) * tanhf(acc[1] + bias);
    hn.z = uu.z * hh.z + (1.f - uu.z) * tanhf(acc[2] + bias);
    hn.w = uu.w * hh.w + (1.f - uu.w) * tanhf(acc[3] + bias);
#pragma unroll
    for (int r = 0; r < CLS; ++r) {
      float* hp = reinterpret_cast<float*>((char*)Sp[r] + hoff);
      *reinterpret_cast<float4*>(hp + oc * Nn + go) = hn;
    }
  }
}

}  // namespace

__global__ void __launch_bounds__(NT, 1) __cluster_dims__(CLS, 1, 1)
dcgru_kernel(
    const float* __restrict__ x_all,   // (B,T,N,DIN)
    const int* __restrict__ seq_len,   // (B)
    const float* __restrict__ support, // (N,N)
    const float* __restrict__ W0g, const float* __restrict__ b0g,
    const float* __restrict__ W0c, const float* __restrict__ b0c,
    const float* __restrict__ W1g, const float* __restrict__ b1g,
    const float* __restrict__ W1c, const float* __restrict__ b1c,
    const float* __restrict__ Wfc, const float* __restrict__ bfc,
    float* __restrict__ out) {         // (B,C)
  extern __shared__ float smraw[];
  Smem& S = *reinterpret_cast<Smem*>(smraw);
  cgx::cluster_group cl = cgx::this_cluster();
  const int rank = cl.block_rank();
  const int b = blockIdx.x / CLS;
  const int tid = threadIdx.x;

  Smem* Sp[CLS];
#pragma unroll
  for (int r = 0; r < CLS; ++r)
    Sp[r] = reinterpret_cast<Smem*>(cl.map_shared_rank(&S, r));

  // Load own 32 rows of support.
  for (int i = tid; i < NP * Nn; i += NT)
    S.P[i] = support[rank * NP * Nn + i];
  __syncthreads();

  // Precompute P2 = (own rows of) support^2. thread = (node, 8 k-values).
  {
    const int n = tid >> 4;
    const int k8 = (tid & 15) * 8;
    const float* Pr = &S.P[n * Nn];
    float acc[8] = {0.f, 0.f, 0.f, 0.f, 0.f, 0.f, 0.f, 0.f};
    for (int m = 0; m < Nn; ++m) {
      const float p = Pr[m];
      const float4 sa = *reinterpret_cast<const float4*>(
          support + (size_t)m * Nn + k8);
      const float4 sb = *reinterpret_cast<const float4*>(
          support + (size_t)m * Nn + k8 + 4);
      acc[0] = fmaf(p, sa.x, acc[0]); acc[1] = fmaf(p, sa.y, acc[1]);
      acc[2] = fmaf(p, sa.z, acc[2]); acc[3] = fmaf(p, sa.w, acc[3]);
      acc[4] = fmaf(p, sb.x, acc[4]); acc[5] = fmaf(p, sb.y, acc[5]);
      acc[6] = fmaf(p, sb.z, acc[6]); acc[7] = fmaf(p, sb.w, acc[7]);
    }
#pragma unroll
    for (int j = 0; j < 8; ++j) S.P2[n * Nn + k8 + j] = acc[j];
  }

  // Zero transposed hidden states.
  for (int i = tid; i < Un * Nn; i += NT) {
    S.th0[i] = 0.f;
    S.th1[i] = 0.f;
  }

  const int tlast = seq_len[b] - 1;  // uniform across the cluster

  for (int t = 0; t <= tlast; ++t) {
    // stage current frame TRANSPOSED: tx[c][n] (swizzled)
    const float4 xv = reinterpret_cast<const float4*>(
        x_all + ((size_t)b * Tn + t) * (Nn * DINn))[tid];
    {
      const int n = tid >> 2;
      const int c0 = (tid & 3) * 4;
      const int k = tid & 3;  // key8(c0+j) for all j<4
      const int base = ((n >> 2) ^ k) * 4 + (n & 3);
      S.tx[(c0 + 0) * Nn + base] = xv.x;
      S.tx[(c0 + 1) * Nn + base] = xv.y;
      S.tx[(c0 + 2) * Nn + base] = xv.z;
      S.tx[(c0 + 3) * Nn + base] = xv.w;
    }
    cell<DINn>(cl, S, Sp, tid, rank, S.tx, S.th0, W0g, b0g, W0c, b0c);
    cell<Un>(cl, S, Sp, tid, rank, S.th0, S.th1, W1g, b1g, W1c, b1c);
  }

  cl.sync();  // all th1 scatters visible in rank 0's copy

  if (rank == 0) {
    // classifier: max_n( relu(h1[n]) @ Wfc + bfc ); t1 is dead, use as scratch
    const int n = tid >> 2;
    const int c = tid & 3;
    float a = 0.f;
#pragma unroll 8
    for (int u = 0; u < Un; ++u) {
      const float hv = S.th1[u * Nn + (((n >> 2) ^ key8(u)) << 2) + (n & 3)];
      a = fmaf(fmaxf(hv, 0.f), Wfc[u * Cn + c], a);
    }
    S.t1[n * Cn + c] = a + bfc[c];
    __syncthreads();
    if (tid < Cn) {
      float m = S.t1[tid];
      for (int n2 = 1; n2 < Nn; ++n2) m = fmaxf(m, S.t1[n2 * Cn + tid]);
      out[b * Cn + tid] = m;
    }
  }
}

extern "C" void kernel_launch(void* const* d_in, const int* in_sizes, int n_in,
                              void* d_out, int out_size) {
  const float* x   = (const float*)d_in[0];
  const int*   sl  = (const int*)d_in[1];
  const float* sup = (const float*)d_in[2];
  const float* W0g = (const float*)d_in[3];
  const float* b0g = (const float*)d_in[4];
  const float* W0c = (const float*)d_in[5];
  const float* b0c = (const float*)d_in[6];
  const float* W1g = (const float*)d_in[7];
  const float* b1g = (const float*)d_in[8];
  const float* W1c = (const float*)d_in[9];
  const float* b1c = (const float*)d_in[10];
  const float* Wfc = (const float*)d_in[11];
  const float* bfc = (const float*)d_in[12];
  float* out = (float*)d_out;

  const size_t smem = sizeof(Smem);
  cudaFuncSetAttribute(dcgru_kernel,
                       cudaFuncAttributeMaxDynamicSharedMemorySize, (int)smem);
  dcgru_kernel<<<Bn * CLS, NT, smem>>>(x, sl, sup, W0g, b0g, W0c, b0c,
                                       W1g, b1g, W1c, b1c, Wfc, bfc, out);
}

// round 15
// speedup vs baseline: 1.6820x; 1.0462x over previous
#include <cuda_runtime.h>
#include <cooperative_groups.h>
#include <math.h>

namespace cgx = cooperative_groups;
#define DEVINL __device__ __forceinline__

namespace {

constexpr int Bn   = 32;   // batch
constexpr int Tn   = 256;  // timesteps
constexpr int Nn   = 128;  // nodes
constexpr int DINn = 16;   // input features
constexpr int Un   = 64;   // hidden units
constexpr int Cn   = 4;    // classes
constexpr int CLS  = 4;    // cluster size (CTAs per batch)
constexpr int NP   = 32;   // nodes owned per CTA
constexpr int NT   = 512;  // threads per CTA

typedef unsigned long long ull;

// packed fp32x2 FMA (sm_103a): d.lo += a.lo*b.lo; d.hi += a.hi*b.hi (exact fp32)
DEVINL void fma2(ull& d, ull a, ull b) {
  asm("fma.rn.f32x2 %0, %1, %2, %0;" : "+l"(d) : "l"(a), "l"(b));
}
DEVINL ull dup2(float a) {
  ull r; asm("mov.b64 %0, {%1, %1};" : "=l"(r) : "f"(a)); return r;
}
DEVINL float2 lohi(ull v) {
  float2 r; asm("mov.b64 {%0, %1}, %2;" : "=f"(r.x), "=f"(r.y) : "l"(v)); return r;
}
DEVINL float rsum(ull v) { const float2 t = lohi(v); return t.x + t.y; }

// Activation buffers TRANSPOSED: t[c][n], 3-bit XOR swizzle on float4 granules.
struct Smem {
  float P[NP * Nn];     // own 32 rows of support           (16 KB)
  float P2[NP * Nn];    // own 32 rows of support^2         (16 KB)
  float tx[DINn * Nn];  // transposed input frame           ( 8 KB)
  float th0[Un * Nn];   // transposed hidden, layer 0       (32 KB)
  float th1[Un * Nn];   // transposed hidden, layer 1       (32 KB)
  float trh[Un * Nn];   // transposed r*h                   (32 KB)
  float t1[Nn * NP];    // P z,   own nodes [c][n local]    (16 KB)
  float t2[Nn * NP];    // 2P^2z - z, own [c][n local]      (16 KB)
  float ub[Un * NP];    // update gate [u][n local]         ( 8 KB)
};                      // 45056 floats = 180224 B

DEVINL int key8(int c) { return (c >> 2) & 7; }

// row base + swizzle key for concat channel c (x-part then h-part)
template <int CH0>
DEVINL const float* zrow(const float* __restrict__ s0t,
                         const float* __restrict__ s1t, int c, int& key) {
  if (c < CH0) { key = key8(c); return s0t + c * Nn; }
  const int ch = c - CH0;
  key = key8(ch);
  return s1t + ch * Nn;
}

// ---- gate hop1 (threads 0-255): t1[c][n] = sum_k P[n][k] z[k][c], LOCAL.
template <int CH0>
DEVINL void hop1g(Smem& S, int t, const float* __restrict__ s0t,
                  const float* __restrict__ s1t) {
  constexpr int CIN = CH0 + Un;
  const int lane = t & 31;
  const int c4 = lane * 4;
  if (c4 >= CIN) return;
  const int n0 = (t >> 5) * 4;
  const float* Pr0 = &S.P[(n0 + 0) * Nn];
  const float* Pr1 = &S.P[(n0 + 1) * Nn];
  const float* Pr2 = &S.P[(n0 + 2) * Nn];
  const float* Pr3 = &S.P[(n0 + 3) * Nn];
  const float* zr[4];
  int zk[4];
#pragma unroll
  for (int j = 0; j < 4; ++j) zr[j] = zrow<CH0>(s0t, s1t, c4 + j, zk[j]);
  ull a2[4][4] = {};
#pragma unroll 2
  for (int k = 0; k < Nn; k += 4) {
    const int g = k >> 2;
    const ulonglong2 p0 = *reinterpret_cast<const ulonglong2*>(Pr0 + k);
    const ulonglong2 p1 = *reinterpret_cast<const ulonglong2*>(Pr1 + k);
    const ulonglong2 p2 = *reinterpret_cast<const ulonglong2*>(Pr2 + k);
    const ulonglong2 p3 = *reinterpret_cast<const ulonglong2*>(Pr3 + k);
#pragma unroll
    for (int j = 0; j < 4; ++j) {
      const ulonglong2 z = *reinterpret_cast<const ulonglong2*>(
          zr[j] + ((g ^ zk[j]) << 2));
      fma2(a2[0][j], p0.x, z.x); fma2(a2[0][j], p0.y, z.y);
      fma2(a2[1][j], p1.x, z.x); fma2(a2[1][j], p1.y, z.y);
      fma2(a2[2][j], p2.x, z.x); fma2(a2[2][j], p2.y, z.y);
      fma2(a2[3][j], p3.x, z.x); fma2(a2[3][j], p3.y, z.y);
    }
  }
  const int gl = n0 >> 2;
  const int tk = lane & 7;  // == key8(c4+j)
#pragma unroll
  for (int j = 0; j < 4; ++j)
    *reinterpret_cast<float4*>(&S.t1[(c4 + j) * NP + ((gl ^ tk) << 2)]) =
        make_float4(rsum(a2[0][j]), rsum(a2[1][j]),
                    rsum(a2[2][j]), rsum(a2[3][j]));
}

// ---- gate hop2 (threads 256-511): t2[c][n] = 2*sum_k P2[n][k] z[k][c] - z[n][c].
template <int CH0>
DEVINL void hop2g(Smem& S, int t, int rank, const float* __restrict__ s0t,
                  const float* __restrict__ s1t) {
  constexpr int CIN = CH0 + Un;
  const int lane = t & 31;
  const int c4 = lane * 4;
  if (c4 >= CIN) return;
  const int n0 = (t >> 5) * 4;
  const float* Pr0 = &S.P2[(n0 + 0) * Nn];
  const float* Pr1 = &S.P2[(n0 + 1) * Nn];
  const float* Pr2 = &S.P2[(n0 + 2) * Nn];
  const float* Pr3 = &S.P2[(n0 + 3) * Nn];
  const float* zr[4];
  int zk[4];
#pragma unroll
  for (int j = 0; j < 4; ++j) zr[j] = zrow<CH0>(s0t, s1t, c4 + j, zk[j]);
  ull a2[4][4] = {};
#pragma unroll 2
  for (int k = 0; k < Nn; k += 4) {
    const int g = k >> 2;
    const ulonglong2 p0 = *reinterpret_cast<const ulonglong2*>(Pr0 + k);
    const ulonglong2 p1 = *reinterpret_cast<const ulonglong2*>(Pr1 + k);
    const ulonglong2 p2 = *reinterpret_cast<const ulonglong2*>(Pr2 + k);
    const ulonglong2 p3 = *reinterpret_cast<const ulonglong2*>(Pr3 + k);
#pragma unroll
    for (int j = 0; j < 4; ++j) {
      const ulonglong2 z = *reinterpret_cast<const ulonglong2*>(
          zr[j] + ((g ^ zk[j]) << 2));
      fma2(a2[0][j], p0.x, z.x); fma2(a2[0][j], p0.y, z.y);
      fma2(a2[1][j], p1.x, z.x); fma2(a2[1][j], p1.y, z.y);
      fma2(a2[2][j], p2.x, z.x); fma2(a2[2][j], p2.y, z.y);
      fma2(a2[3][j], p3.x, z.x); fma2(a2[3][j], p3.y, z.y);
    }
  }
  const int gl = n0 >> 2;
  const int g0 = (rank * NP + n0) >> 2;
  const int tk = lane & 7;
#pragma unroll
  for (int j = 0; j < 4; ++j) {
    const float4 z0 = *reinterpret_cast<const float4*>(
        zr[j] + ((g0 ^ zk[j]) << 2));
    *reinterpret_cast<float4*>(&S.t2[(c4 + j) * NP + ((gl ^ tk) << 2)]) =
        make_float4(2.f * rsum(a2[0][j]) - z0.x, 2.f * rsum(a2[1][j]) - z0.y,
                    2.f * rsum(a2[2][j]) - z0.z, 2.f * rsum(a2[3][j]) - z0.w);
  }
}

// ---- candidate hop1 (threads 0-255): rh channels only -> t1 rows [CH0, CH0+64).
template <int CH0>
DEVINL void hop1cd(Smem& S, int t) {
  const int cn = t & 15;
  const int ch4 = cn * 4;
  const int tk = cn & 7;  // key8(ch4+j) in trh
  const int n0 = (t >> 4) * 2;
  const float* Pr0 = &S.P[(n0 + 0) * Nn];
  const float* Pr1 = &S.P[(n0 + 1) * Nn];
  const float* zr[4];
#pragma unroll
  for (int j = 0; j < 4; ++j) zr[j] = &S.trh[(ch4 + j) * Nn];
  ull a2[2][4] = {};
#pragma unroll 2
  for (int k = 0; k < Nn; k += 4) {
    const int g = (k >> 2) ^ tk;
    const ulonglong2 p0 = *reinterpret_cast<const ulonglong2*>(Pr0 + k);
    const ulonglong2 p1 = *reinterpret_cast<const ulonglong2*>(Pr1 + k);
#pragma unroll
    for (int j = 0; j < 4; ++j) {
      const ulonglong2 z = *reinterpret_cast<const ulonglong2*>(zr[j] + (g << 2));
      fma2(a2[0][j], p0.x, z.x); fma2(a2[0][j], p0.y, z.y);
      fma2(a2[1][j], p1.x, z.x); fma2(a2[1][j], p1.y, z.y);
    }
  }
  const int ksd = ((CH0 >> 2) + cn) & 7;  // key8 of destination row CH0+ch4+j
  const int gl = n0 >> 2, ofl = n0 & 3;
#pragma unroll
  for (int j = 0; j < 4; ++j)
    *reinterpret_cast<float2*>(
        &S.t1[(CH0 + ch4 + j) * NP + ((gl ^ ksd) << 2) + ofl]) =
        make_float2(rsum(a2[0][j]), rsum(a2[1][j]));
}

// ---- candidate hop2 (threads 256-511): rh channels via P2 -> t2.
template <int CH0>
DEVINL void hop2cd(Smem& S, int t, int rank) {
  const int cn = t & 15;
  const int ch4 = cn * 4;
  const int tk = cn & 7;
  const int n0 = (t >> 4) * 2;
  const float* Pr0 = &S.P2[(n0 + 0) * Nn];
  const float* Pr1 = &S.P2[(n0 + 1) * Nn];
  const float* zr[4];
#pragma unroll
  for (int j = 0; j < 4; ++j) zr[j] = &S.trh[(ch4 + j) * Nn];
  ull a2[2][4] = {};
#pragma unroll 2
  for (int k = 0; k < Nn; k += 4) {
    const int g = (k >> 2) ^ tk;
    const ulonglong2 p0 = *reinterpret_cast<const ulonglong2*>(Pr0 + k);
    const ulonglong2 p1 = *reinterpret_cast<const ulonglong2*>(Pr1 + k);
#pragma unroll
    for (int j = 0; j < 4; ++j) {
      const ulonglong2 z = *reinterpret_cast<const ulonglong2*>(zr[j] + (g << 2));
      fma2(a2[0][j], p0.x, z.x); fma2(a2[0][j], p0.y, z.y);
      fma2(a2[1][j], p1.x, z.x); fma2(a2[1][j], p1.y, z.y);
    }
  }
  const int ksd = ((CH0 >> 2) + cn) & 7;
  const int ng0 = rank * NP + n0;
  const int gw = ng0 >> 2, ofs = ng0 & 3;
  const int gl = n0 >> 2, ofl = n0 & 3;
#pragma unroll
  for (int j = 0; j < 4; ++j) {
    const float2 z0 = *reinterpret_cast<const float2*>(
        &S.trh[(ch4 + j) * Nn + ((gw ^ tk) << 2) + ofs]);
    *reinterpret_cast<float2*>(
        &S.t2[(CH0 + ch4 + j) * NP + ((gl ^ ksd) << 2) + ofl]) =
        make_float2(2.f * rsum(a2[0][j]) - z0.x, 2.f * rsum(a2[1][j]) - z0.y);
  }
}

// ---- projection inner part, QUAD-HOISTED: swizzle keys and base addresses
// computed once per 4 channels; the unrolled j-loop uses immediate offsets.
// zbase: transposed source buffer (row stride Nn, keys = key8(local row)).
// c0:    concat-channel offset of this part (selects t1/t2 rows + their keys).
template <int COUT, int NPT, int NCH>
DEVINL void accum_part(Smem& S, const float* __restrict__ zbase, int c0,
                       const float* __restrict__ Wp0, int g1, int g2,
                       ull* __restrict__ acc2) {
  const float* Wp = Wp0;
#pragma unroll 2
  for (int q = 0; q < NCH / 4; ++q) {
    const int kz = q & 7;                // key8 of zbase rows 4q..4q+3
    const int kd = ((c0 >> 2) + q) & 7;  // key8 of t1/t2 rows c0+4q..
    const float* z0p = zbase + (q * 4) * Nn + ((g1 ^ kz) << 2);
    const float* t1p = &S.t1[(c0 + q * 4) * NP + ((g2 ^ kd) << 2)];
    const float* t2p = &S.t2[(c0 + q * 4) * NP + ((g2 ^ kd) << 2)];
    const float* z0q = zbase + (q * 4) * Nn + (((g1 + 1) ^ kz) << 2);
    const float* t1q = &S.t1[(c0 + q * 4) * NP + (((g2 + 1) ^ kd) << 2)];
    const float* t2q = &S.t2[(c0 + q * 4) * NP + (((g2 + 1) ^ kd) << 2)];
#pragma unroll
    for (int j = 0; j < 4; ++j) {
      const ull w0 = dup2(Wp[(3 * j + 0) * COUT]);
      const ull w1 = dup2(Wp[(3 * j + 1) * COUT]);
      const ull w2 = dup2(Wp[(3 * j + 2) * COUT]);
      const ulonglong2 z0 = *reinterpret_cast<const ulonglong2*>(z0p + j * Nn);
      const ulonglong2 z1 = *reinterpret_cast<const ulonglong2*>(t1p + j * NP);
      const ulonglong2 z2 = *reinterpret_cast<const ulonglong2*>(t2p + j * NP);
      fma2(acc2[0], z0.x, w0); fma2(acc2[0], z1.x, w1); fma2(acc2[0], z2.x, w2);
      fma2(acc2[1], z0.y, w0); fma2(acc2[1], z1.y, w1); fma2(acc2[1], z2.y, w2);
      if (NPT == 8) {
        const ulonglong2 z0b = *reinterpret_cast<const ulonglong2*>(z0q + j * Nn);
        const ulonglong2 z1b = *reinterpret_cast<const ulonglong2*>(t1q + j * NP);
        const ulonglong2 z2b = *reinterpret_cast<const ulonglong2*>(t2q + j * NP);
        fma2(acc2[2], z0b.x, w0); fma2(acc2[2], z1b.x, w1); fma2(acc2[2], z2b.x, w2);
        fma2(acc2[3], z0b.y, w0); fma2(acc2[3], z1b.y, w1); fma2(acc2[3], z2b.y, w2);
      }
    }
    Wp += 12 * COUT;
  }
}

// ---- projection: oc = tid & (COUT-1) -> coalesced W; z loads broadcast.
template <int CH0, int COUT, int NPT>
DEVINL void accum(Smem& S, int tid, int rank, const float* __restrict__ W,
                  const float* __restrict__ s0t, const float* __restrict__ s1t,
                  ull* __restrict__ acc2) {
  const int oc = tid & (COUT - 1);
  const int n0 = (tid / COUT) * NPT;
  const int g1 = (rank * NP + n0) >> 2;  // global granule (replicated z0)
  const int g2 = n0 >> 2;                // local granule (t1, t2)
  accum_part<COUT, NPT, CH0>(S, s0t, 0, W + oc, g1, g2, acc2);
  accum_part<COUT, NPT, Un>(S, s1t, CH0,
                            W + (size_t)(3 * CH0) * COUT + oc, g1, g2, acc2);
}

// ---- one DCGRU cell, cluster-cooperative; ht = this layer's transposed h.
template <int CH0>
DEVINL void cell(cgx::cluster_group& cl, Smem& S, Smem* const* Sp, int tid,
                 int rank, const float* __restrict__ s0t, float* __restrict__ ht,
                 const float* __restrict__ Wg, const float* __restrict__ bg,
                 const float* __restrict__ Wc, const float* __restrict__ bc) {
  const size_t hoff = (size_t)((const char*)ht - (const char*)&S);

  // ================= gate =================
  cl.sync();  // replicated inputs (h / trh / h-scatters) visible everywhere
  if (tid < 256) hop1g<CH0>(S, tid, s0t, ht);
  else           hop2g<CH0>(S, tid - 256, rank, s0t, ht);
  __syncthreads();
  {
    ull acc2[4] = {0ull, 0ull, 0ull, 0ull};
    accum<CH0, 128, 8>(S, tid, rank, Wg, s0t, ht, acc2);
    float acc[8];
#pragma unroll
    for (int q = 0; q < 4; ++q) {
      const float2 t = lohi(acc2[q]);
      acc[2 * q] = t.x;
      acc[2 * q + 1] = t.y;
    }
    const int oc = tid & 127;        // matches accum remap
    const int n0 = (tid >> 7) * 8;
    const int ng0 = rank * NP + n0;
    const float bias = bg[oc];
    float v[8];
#pragma unroll
    for (int i = 0; i < 8; ++i)
      v[i] = 1.f / (1.f + __expf(-(acc[i] + bias)));
    if (oc < Un) {  // r-part -> trh (transposed), scattered to all ranks
      const int k = key8(oc);
      const int g = ng0 >> 2;
      const float* hr = ht + oc * Nn;
      const float4 h0 = *reinterpret_cast<const float4*>(hr + ((g ^ k) << 2));
      const float4 h1 = *reinterpret_cast<const float4*>(hr + (((g + 1) ^ k) << 2));
      const float4 r0 = make_float4(v[0] * h0.x, v[1] * h0.y, v[2] * h0.z, v[3] * h0.w);
      const float4 r1 = make_float4(v[4] * h1.x, v[5] * h1.y, v[6] * h1.z, v[7] * h1.w);
#pragma unroll
      for (int r = 0; r < CLS; ++r) {
        float* base = &Sp[r]->trh[oc * Nn];
        *reinterpret_cast<float4*>(base + ((g ^ k) << 2)) = r0;
        *reinterpret_cast<float4*>(base + (((g + 1) ^ k) << 2)) = r1;
      }
    } else {  // u-part -> local ub (transposed)
      const int ou = oc - Un;
      const int ku = key8(ou);
      const int gl = n0 >> 2;
      float* ur = &S.ub[ou * NP];
      *reinterpret_cast<float4*>(ur + ((gl ^ ku) << 2)) =
          make_float4(v[0], v[1], v[2], v[3]);
      *reinterpret_cast<float4*>(ur + (((gl + 1) ^ ku) << 2)) =
          make_float4(v[4], v[5], v[6], v[7]);
    }
  }

  // ================= candidate + update =================
  cl.sync();  // trh gathered; all ranks past gate accum
  if (tid < 256) hop1cd<CH0>(S, tid);
  else           hop2cd<CH0>(S, tid - 256, rank);
  __syncthreads();
  {
    ull acc2[2] = {0ull, 0ull};
    accum<CH0, 64, 4>(S, tid, rank, Wc, s0t, S.trh, acc2);
    float acc[4];
    {
      float2 t = lohi(acc2[0]);
      acc[0] = t.x; acc[1] = t.y;
      t = lohi(acc2[1]);
      acc[2] = t.x; acc[3] = t.y;
    }
    const int oc = tid & 63;         // matches accum remap
    const int n0 = (tid >> 6) * 4;
    const int ng0 = rank * NP + n0;
    const int k = key8(oc);
    const float bias = bc[oc];
    const float4 uu = *reinterpret_cast<const float4*>(
        &S.ub[oc * NP] + (((n0 >> 2) ^ k) << 2));
    const int go = ((ng0 >> 2) ^ k) << 2;
    const float4 hh = *reinterpret_cast<const float4*>(ht + oc * Nn + go);
    float4 hn;
    hn.x = uu.x * hh.x + (1.f - uu.x) * tanhf(acc[0] + bias);
    hn.y = uu.y * hh.y + (1.f - uu.y) * tanhf(acc[1] + bias);
    hn.z = uu.z * hh.z + (1.f - uu.z) * tanhf(acc[2] + bias);
    hn.w = uu.w * hh.w + (1.f - uu.w) * tanhf(acc[3] + bias);
#pragma unroll
    for (int r = 0; r < CLS; ++r) {
      float* hp = reinterpret_cast<float*>((char*)Sp[r] + hoff);
      *reinterpret_cast<float4*>(hp + oc * Nn + go) = hn;
    }
  }
}

}  // namespace

__global__ void __launch_bounds__(NT, 1) __cluster_dims__(CLS, 1, 1)
dcgru_kernel(
    const float* __restrict__ x_all,   // (B,T,N,DIN)
    const int* __restrict__ seq_len,   // (B)
    const float* __restrict__ support, // (N,N)
    const float* __restrict__ W0g, const float* __restrict__ b0g,
    const float* __restrict__ W0c, const float* __restrict__ b0c,
    const float* __restrict__ W1g, const float* __restrict__ b1g,
    const float* __restrict__ W1c, const float* __restrict__ b1c,
    const float* __restrict__ Wfc, const float* __restrict__ bfc,
    float* __restrict__ out) {         // (B,C)
  extern __shared__ float smraw[];
  Smem& S = *reinterpret_cast<Smem*>(smraw);
  cgx::cluster_group cl = cgx::this_cluster();
  const int rank = cl.block_rank();
  const int b = blockIdx.x / CLS;
  const int tid = threadIdx.x;

  Smem* Sp[CLS];
#pragma unroll
  for (int r = 0; r < CLS; ++r)
    Sp[r] = reinterpret_cast<Smem*>(cl.map_shared_rank(&S, r));

  // Load own 32 rows of support.
  for (int i = tid; i < NP * Nn; i += NT)
    S.P[i] = support[rank * NP * Nn + i];
  __syncthreads();

  // Precompute P2 = (own rows of) support^2. thread = (node, 8 k-values).
  {
    const int n = tid >> 4;
    const int k8 = (tid & 15) * 8;
    const float* Pr = &S.P[n * Nn];
    float acc[8] = {0.f, 0.f, 0.f, 0.f, 0.f, 0.f, 0.f, 0.f};
    for (int m = 0; m < Nn; ++m) {
      const float p = Pr[m];
      const float4 sa = *reinterpret_cast<const float4*>(
          support + (size_t)m * Nn + k8);
      const float4 sb = *reinterpret_cast<const float4*>(
          support + (size_t)m * Nn + k8 + 4);
      acc[0] = fmaf(p, sa.x, acc[0]); acc[1] = fmaf(p, sa.y, acc[1]);
      acc[2] = fmaf(p, sa.z, acc[2]); acc[3] = fmaf(p, sa.w, acc[3]);
      acc[4] = fmaf(p, sb.x, acc[4]); acc[5] = fmaf(p, sb.y, acc[5]);
      acc[6] = fmaf(p, sb.z, acc[6]); acc[7] = fmaf(p, sb.w, acc[7]);
    }
#pragma unroll
    for (int j = 0; j < 8; ++j) S.P2[n * Nn + k8 + j] = acc[j];
  }

  // Zero transposed hidden states.
  for (int i = tid; i < Un * Nn; i += NT) {
    S.th0[i] = 0.f;
    S.th1[i] = 0.f;
  }

  const int tlast = seq_len[b] - 1;  // uniform across the cluster

  for (int t = 0; t <= tlast; ++t) {
    // stage current frame TRANSPOSED: tx[c][n] (swizzled)
    const float4 xv = reinterpret_cast<const float4*>(
        x_all + ((size_t)b * Tn + t) * (Nn * DINn))[tid];
    {
      const int n = tid >> 2;
      const int c0 = (tid & 3) * 4;
      const int k = tid & 3;  // key8(c0+j) for all j<4
      const int base = ((n >> 2) ^ k) * 4 + (n & 3);
      S.tx[(c0 + 0) * Nn + base] = xv.x;
      S.tx[(c0 + 1) * Nn + base] = xv.y;
      S.tx[(c0 + 2) * Nn + base] = xv.z;
      S.tx[(c0 + 3) * Nn + base] = xv.w;
    }
    cell<DINn>(cl, S, Sp, tid, rank, S.tx, S.th0, W0g, b0g, W0c, b0c);
    cell<Un>(cl, S, Sp, tid, rank, S.th0, S.th1, W1g, b1g, W1c, b1c);
  }

  cl.sync();  // all th1 scatters visible in rank 0's copy

  if (rank == 0) {
    // classifier: max_n( relu(h1[n]) @ Wfc + bfc ); t1 is dead, use as scratch
    const int n = tid >> 2;
    const int c = tid & 3;
    float a = 0.f;
#pragma unroll 8
    for (int u = 0; u < Un; ++u) {
      const float hv = S.th1[u * Nn + (((n >> 2) ^ key8(u)) << 2) + (n & 3)];
      a = fmaf(fmaxf(hv, 0.f), Wfc[u * Cn + c], a);
    }
    S.t1[n * Cn + c] = a + bfc[c];
    __syncthreads();
    if (tid < Cn) {
      float m = S.t1[tid];
      for (int n2 = 1; n2 < Nn; ++n2) m = fmaxf(m, S.t1[n2 * Cn + tid]);
      out[b * Cn + tid] = m;
    }
  }
}

extern "C" void kernel_launch(void* const* d_in, const int* in_sizes, int n_in,
                              void* d_out, int out_size) {
  const float* x   = (const float*)d_in[0];
  const int*   sl  = (const int*)d_in[1];
  const float* sup = (const float*)d_in[2];
  const float* W0g = (const float*)d_in[3];
  const float* b0g = (const float*)d_in[4];
  const float* W0c = (const float*)d_in[5];
  const float* b0c = (const float*)d_in[6];
  const float* W1g = (const float*)d_in[7];
  const float* b1g = (const float*)d_in[8];
  const float* W1c = (const float*)d_in[9];
  const float* b1c = (const float*)d_in[10];
  const float* Wfc = (const float*)d_in[11];
  const float* bfc = (const float*)d_in[12];
  float* out = (float*)d_out;

  const size_t smem = sizeof(Smem);
  cudaFuncSetAttribute(dcgru_kernel,
                       cudaFuncAttributeMaxDynamicSharedMemorySize, (int)smem);
  dcgru_kernel<<<Bn * CLS, NT, smem>>>(x, sl, sup, W0g, b0g, W0c, b0c,
                                       W1g, b1g, W1c, b1c, Wfc, bfc, out);
}

// round 16
// speedup vs baseline: 1.6854x; 1.0020x over previous
#include <cuda_runtime.h>
#include <cooperative_groups.h>
#include <math.h>

namespace cgx = cooperative_groups;
#define DEVINL __device__ __forceinline__

namespace {

constexpr int Bn   = 32;   // batch
constexpr int Tn   = 256;  // timesteps
constexpr int Nn   = 128;  // nodes
constexpr int DINn = 16;   // input features
constexpr int Un   = 64;   // hidden units
constexpr int Cn   = 4;    // classes
constexpr int CLS  = 4;    // cluster size (CTAs per batch)
constexpr int NP   = 32;   // nodes owned per CTA
constexpr int NT   = 512;  // threads per CTA

typedef unsigned long long ull;

// packed fp32x2 FMA (sm_103a): d.lo += a.lo*b.lo; d.hi += a.hi*b.hi (exact fp32)
DEVINL void fma2(ull& d, ull a, ull b) {
  asm("fma.rn.f32x2 %0, %1, %2, %0;" : "+l"(d) : "l"(a), "l"(b));
}
DEVINL ull dup2(float a) {
  ull r; asm("mov.b64 %0, {%1, %1};" : "=l"(r) : "f"(a)); return r;
}
DEVINL float2 lohi(ull v) {
  float2 r; asm("mov.b64 {%0, %1}, %2;" : "=f"(r.x), "=f"(r.y) : "l"(v)); return r;
}
DEVINL float rsum(ull v) { const float2 t = lohi(v); return t.x + t.y; }

// Activation buffers TRANSPOSED: t[c][n], 3-bit XOR swizzle on float4 granules.
struct Smem {
  float P[NP * Nn];     // own 32 rows of support           (16 KB)
  float P2[NP * Nn];    // own 32 rows of support^2         (16 KB)
  float tx[DINn * Nn];  // transposed input frame           ( 8 KB)
  float th0[Un * Nn];   // transposed hidden, layer 0       (32 KB)
  float th1[Un * Nn];   // transposed hidden, layer 1       (32 KB)
  float trh[Un * Nn];   // transposed r*h                   (32 KB)
  float t1[Nn * NP];    // P z,   own nodes [c][n local]    (16 KB)
  float t2[Nn * NP];    // 2P^2z - z, own [c][n local]      (16 KB)
  float ub[Un * NP];    // update gate [u][n local]         ( 8 KB)
};                      // 45056 floats = 180224 B

DEVINL int key8(int c) { return (c >> 2) & 7; }

// row base + swizzle key for concat channel c (x-part then h-part)
template <int CH0>
DEVINL const float* zrow(const float* __restrict__ s0t,
                         const float* __restrict__ s1t, int c, int& key) {
  if (c < CH0) { key = key8(c); return s0t + c * Nn; }
  const int ch = c - CH0;
  key = key8(ch);
  return s1t + ch * Nn;
}

// ---- gate hop1 (threads 0-255): t1[c][n] = sum_k P[n][k] z[k][c], LOCAL.
template <int CH0>
DEVINL void hop1g(Smem& S, int t, const float* __restrict__ s0t,
                  const float* __restrict__ s1t) {
  constexpr int CIN = CH0 + Un;
  const int lane = t & 31;
  const int c4 = lane * 4;
  if (c4 >= CIN) return;
  const int n0 = (t >> 5) * 4;
  const float* Pr0 = &S.P[(n0 + 0) * Nn];
  const float* Pr1 = &S.P[(n0 + 1) * Nn];
  const float* Pr2 = &S.P[(n0 + 2) * Nn];
  const float* Pr3 = &S.P[(n0 + 3) * Nn];
  const float* zr[4];
  int zk[4];
#pragma unroll
  for (int j = 0; j < 4; ++j) zr[j] = zrow<CH0>(s0t, s1t, c4 + j, zk[j]);
  ull a2[4][4] = {};
#pragma unroll 2
  for (int k = 0; k < Nn; k += 4) {
    const int g = k >> 2;
    const ulonglong2 p0 = *reinterpret_cast<const ulonglong2*>(Pr0 + k);
    const ulonglong2 p1 = *reinterpret_cast<const ulonglong2*>(Pr1 + k);
    const ulonglong2 p2 = *reinterpret_cast<const ulonglong2*>(Pr2 + k);
    const ulonglong2 p3 = *reinterpret_cast<const ulonglong2*>(Pr3 + k);
#pragma unroll
    for (int j = 0; j < 4; ++j) {
      const ulonglong2 z = *reinterpret_cast<const ulonglong2*>(
          zr[j] + ((g ^ zk[j]) << 2));
      fma2(a2[0][j], p0.x, z.x); fma2(a2[0][j], p0.y, z.y);
      fma2(a2[1][j], p1.x, z.x); fma2(a2[1][j], p1.y, z.y);
      fma2(a2[2][j], p2.x, z.x); fma2(a2[2][j], p2.y, z.y);
      fma2(a2[3][j], p3.x, z.x); fma2(a2[3][j], p3.y, z.y);
    }
  }
  const int gl = n0 >> 2;
  const int tk = lane & 7;  // == key8(c4+j)
#pragma unroll
  for (int j = 0; j < 4; ++j)
    *reinterpret_cast<float4*>(&S.t1[(c4 + j) * NP + ((gl ^ tk) << 2)]) =
        make_float4(rsum(a2[0][j]), rsum(a2[1][j]),
                    rsum(a2[2][j]), rsum(a2[3][j]));
}

// ---- gate hop2 (threads 256-511): t2[c][n] = 2*sum_k P2[n][k] z[k][c] - z[n][c].
template <int CH0>
DEVINL void hop2g(Smem& S, int t, int rank, const float* __restrict__ s0t,
                  const float* __restrict__ s1t) {
  constexpr int CIN = CH0 + Un;
  const int lane = t & 31;
  const int c4 = lane * 4;
  if (c4 >= CIN) return;
  const int n0 = (t >> 5) * 4;
  const float* Pr0 = &S.P2[(n0 + 0) * Nn];
  const float* Pr1 = &S.P2[(n0 + 1) * Nn];
  const float* Pr2 = &S.P2[(n0 + 2) * Nn];
  const float* Pr3 = &S.P2[(n0 + 3) * Nn];
  const float* zr[4];
  int zk[4];
#pragma unroll
  for (int j = 0; j < 4; ++j) zr[j] = zrow<CH0>(s0t, s1t, c4 + j, zk[j]);
  ull a2[4][4] = {};
#pragma unroll 2
  for (int k = 0; k < Nn; k += 4) {
    const int g = k >> 2;
    const ulonglong2 p0 = *reinterpret_cast<const ulonglong2*>(Pr0 + k);
    const ulonglong2 p1 = *reinterpret_cast<const ulonglong2*>(Pr1 + k);
    const ulonglong2 p2 = *reinterpret_cast<const ulonglong2*>(Pr2 + k);
    const ulonglong2 p3 = *reinterpret_cast<const ulonglong2*>(Pr3 + k);
#pragma unroll
    for (int j = 0; j < 4; ++j) {
      const ulonglong2 z = *reinterpret_cast<const ulonglong2*>(
          zr[j] + ((g ^ zk[j]) << 2));
      fma2(a2[0][j], p0.x, z.x); fma2(a2[0][j], p0.y, z.y);
      fma2(a2[1][j], p1.x, z.x); fma2(a2[1][j], p1.y, z.y);
      fma2(a2[2][j], p2.x, z.x); fma2(a2[2][j], p2.y, z.y);
      fma2(a2[3][j], p3.x, z.x); fma2(a2[3][j], p3.y, z.y);
    }
  }
  const int gl = n0 >> 2;
  const int g0 = (rank * NP + n0) >> 2;
  const int tk = lane & 7;
#pragma unroll
  for (int j = 0; j < 4; ++j) {
    const float4 z0 = *reinterpret_cast<const float4*>(
        zr[j] + ((g0 ^ zk[j]) << 2));
    *reinterpret_cast<float4*>(&S.t2[(c4 + j) * NP + ((gl ^ tk) << 2)]) =
        make_float4(2.f * rsum(a2[0][j]) - z0.x, 2.f * rsum(a2[1][j]) - z0.y,
                    2.f * rsum(a2[2][j]) - z0.z, 2.f * rsum(a2[3][j]) - z0.w);
  }
}

// ---- candidate hop1 (threads 0-255): rh channels only -> t1 rows [CH0, CH0+64).
template <int CH0>
DEVINL void hop1cd(Smem& S, int t) {
  const int cn = t & 15;
  const int ch4 = cn * 4;
  const int tk = cn & 7;  // key8(ch4+j) in trh
  const int n0 = (t >> 4) * 2;
  const float* Pr0 = &S.P[(n0 + 0) * Nn];
  const float* Pr1 = &S.P[(n0 + 1) * Nn];
  const float* zr[4];
#pragma unroll
  for (int j = 0; j < 4; ++j) zr[j] = &S.trh[(ch4 + j) * Nn];
  ull a2[2][4] = {};
#pragma unroll 2
  for (int k = 0; k < Nn; k += 4) {
    const int g = (k >> 2) ^ tk;
    const ulonglong2 p0 = *reinterpret_cast<const ulonglong2*>(Pr0 + k);
    const ulonglong2 p1 = *reinterpret_cast<const ulonglong2*>(Pr1 + k);
#pragma unroll
    for (int j = 0; j < 4; ++j) {
      const ulonglong2 z = *reinterpret_cast<const ulonglong2*>(zr[j] + (g << 2));
      fma2(a2[0][j], p0.x, z.x); fma2(a2[0][j], p0.y, z.y);
      fma2(a2[1][j], p1.x, z.x); fma2(a2[1][j], p1.y, z.y);
    }
  }
  const int ksd = ((CH0 >> 2) + cn) & 7;  // key8 of destination row CH0+ch4+j
  const int gl = n0 >> 2, ofl = n0 & 3;
#pragma unroll
  for (int j = 0; j < 4; ++j)
    *reinterpret_cast<float2*>(
        &S.t1[(CH0 + ch4 + j) * NP + ((gl ^ ksd) << 2) + ofl]) =
        make_float2(rsum(a2[0][j]), rsum(a2[1][j]));
}

// ---- candidate hop2 (threads 256-511): rh channels via P2 -> t2.
template <int CH0>
DEVINL void hop2cd(Smem& S, int t, int rank) {
  const int cn = t & 15;
  const int ch4 = cn * 4;
  const int tk = cn & 7;
  const int n0 = (t >> 4) * 2;
  const float* Pr0 = &S.P2[(n0 + 0) * Nn];
  const float* Pr1 = &S.P2[(n0 + 1) * Nn];
  const float* zr[4];
#pragma unroll
  for (int j = 0; j < 4; ++j) zr[j] = &S.trh[(ch4 + j) * Nn];
  ull a2[2][4] = {};
#pragma unroll 2
  for (int k = 0; k < Nn; k += 4) {
    const int g = (k >> 2) ^ tk;
    const ulonglong2 p0 = *reinterpret_cast<const ulonglong2*>(Pr0 + k);
    const ulonglong2 p1 = *reinterpret_cast<const ulonglong2*>(Pr1 + k);
#pragma unroll
    for (int j = 0; j < 4; ++j) {
      const ulonglong2 z = *reinterpret_cast<const ulonglong2*>(zr[j] + (g << 2));
      fma2(a2[0][j], p0.x, z.x); fma2(a2[0][j], p0.y, z.y);
      fma2(a2[1][j], p1.x, z.x); fma2(a2[1][j], p1.y, z.y);
    }
  }
  const int ksd = ((CH0 >> 2) + cn) & 7;
  const int ng0 = rank * NP + n0;
  const int gw = ng0 >> 2, ofs = ng0 & 3;
  const int gl = n0 >> 2, ofl = n0 & 3;
#pragma unroll
  for (int j = 0; j < 4; ++j) {
    const float2 z0 = *reinterpret_cast<const float2*>(
        &S.trh[(ch4 + j) * Nn + ((gw ^ tk) << 2) + ofs]);
    *reinterpret_cast<float2*>(
        &S.t2[(CH0 + ch4 + j) * NP + ((gl ^ ksd) << 2) + ofl]) =
        make_float2(2.f * rsum(a2[0][j]) - z0.x, 2.f * rsum(a2[1][j]) - z0.y);
  }
}

// ---- compute one 4-channel quad with PRELOADED W registers w[12].
template <int COUT, int NPT>
DEVINL void accum_quad(Smem& S, const float* __restrict__ zbase, int c0, int q,
                       int g1, int g2, const float* __restrict__ w,
                       ull* __restrict__ acc2) {
  const int kz = q & 7;                // key8 of zbase rows 4q..4q+3
  const int kd = ((c0 >> 2) + q) & 7;  // key8 of t1/t2 rows c0+4q..
  const float* z0p = zbase + (q * 4) * Nn + ((g1 ^ kz) << 2);
  const float* t1p = &S.t1[(c0 + q * 4) * NP + ((g2 ^ kd) << 2)];
  const float* t2p = &S.t2[(c0 + q * 4) * NP + ((g2 ^ kd) << 2)];
  const float* z0q = zbase + (q * 4) * Nn + (((g1 + 1) ^ kz) << 2);
  const float* t1q = &S.t1[(c0 + q * 4) * NP + (((g2 + 1) ^ kd) << 2)];
  const float* t2q = &S.t2[(c0 + q * 4) * NP + (((g2 + 1) ^ kd) << 2)];
#pragma unroll
  for (int j = 0; j < 4; ++j) {
    const ull w0 = dup2(w[3 * j + 0]);
    const ull w1 = dup2(w[3 * j + 1]);
    const ull w2 = dup2(w[3 * j + 2]);
    const ulonglong2 z0 = *reinterpret_cast<const ulonglong2*>(z0p + j * Nn);
    const ulonglong2 z1 = *reinterpret_cast<const ulonglong2*>(t1p + j * NP);
    const ulonglong2 z2 = *reinterpret_cast<const ulonglong2*>(t2p + j * NP);
    fma2(acc2[0], z0.x, w0); fma2(acc2[0], z1.x, w1); fma2(acc2[0], z2.x, w2);
    fma2(acc2[1], z0.y, w0); fma2(acc2[1], z1.y, w1); fma2(acc2[1], z2.y, w2);
    if (NPT == 8) {
      const ulonglong2 z0b = *reinterpret_cast<const ulonglong2*>(z0q + j * Nn);
      const ulonglong2 z1b = *reinterpret_cast<const ulonglong2*>(t1q + j * NP);
      const ulonglong2 z2b = *reinterpret_cast<const ulonglong2*>(t2q + j * NP);
      fma2(acc2[2], z0b.x, w0); fma2(acc2[2], z1b.x, w1); fma2(acc2[2], z2b.x, w2);
      fma2(acc2[3], z0b.y, w0); fma2(acc2[3], z1b.y, w1); fma2(acc2[3], z2b.y, w2);
    }
  }
}

// ---- projection inner part: software-pipelined W double-buffer.
// Quad q+1's 12 W values are LDG'd into the alternate register buffer BEFORE
// quad q's compute, so the ~240-cyc L2 latency is hidden under the ~4x96-issue
// compute window. Even/odd structure keeps all register indices compile-time.
template <int COUT, int NPT, int NCH>
DEVINL void accum_part(Smem& S, const float* __restrict__ zbase, int c0,
                       const float* __restrict__ Wp0, int g1, int g2,
                       ull* __restrict__ acc2) {
  constexpr int NQ = NCH / 4;  // always even (4, 16, or 32)
  float wa[12], wb[12];
#pragma unroll
  for (int r = 0; r < 12; ++r) wa[r] = Wp0[r * COUT];
#pragma unroll 2
  for (int q = 0; q < NQ; q += 2) {
    {  // prefetch quad q+1 (always exists: NQ even)
      const float* Wn = Wp0 + (size_t)(12 * (q + 1)) * COUT;
#pragma unroll
      for (int r = 0; r < 12; ++r) wb[r] = Wn[r * COUT];
    }
    accum_quad<COUT, NPT>(S, zbase, c0, q, g1, g2, wa, acc2);
    if (q + 2 < NQ) {  // prefetch quad q+2 (predicated off on last iter)
      const float* Wn = Wp0 + (size_t)(12 * (q + 2)) * COUT;
#pragma unroll
      for (int r = 0; r < 12; ++r) wa[r] = Wn[r * COUT];
    }
    accum_quad<COUT, NPT>(S, zbase, c0, q + 1, g1, g2, wb, acc2);
  }
}

// ---- projection: oc = tid & (COUT-1) -> coalesced W; z loads broadcast.
template <int CH0, int COUT, int NPT>
DEVINL void accum(Smem& S, int tid, int rank, const float* __restrict__ W,
                  const float* __restrict__ s0t, const float* __restrict__ s1t,
                  ull* __restrict__ acc2) {
  const int oc = tid & (COUT - 1);
  const int n0 = (tid / COUT) * NPT;
  const int g1 = (rank * NP + n0) >> 2;  // global granule (replicated z0)
  const int g2 = n0 >> 2;                // local granule (t1, t2)
  accum_part<COUT, NPT, CH0>(S, s0t, 0, W + oc, g1, g2, acc2);
  accum_part<COUT, NPT, Un>(S, s1t, CH0,
                            W + (size_t)(3 * CH0) * COUT + oc, g1, g2, acc2);
}

// ---- one DCGRU cell, cluster-cooperative; ht = this layer's transposed h.
template <int CH0>
DEVINL void cell(cgx::cluster_group& cl, Smem& S, Smem* const* Sp, int tid,
                 int rank, const float* __restrict__ s0t, float* __restrict__ ht,
                 const float* __restrict__ Wg, const float* __restrict__ bg,
                 const float* __restrict__ Wc, const float* __restrict__ bc) {
  const size_t hoff = (size_t)((const char*)ht - (const char*)&S);

  // ================= gate =================
  cl.sync();  // replicated inputs (h / trh / h-scatters) visible everywhere
  if (tid < 256) hop1g<CH0>(S, tid, s0t, ht);
  else           hop2g<CH0>(S, tid - 256, rank, s0t, ht);
  __syncthreads();
  {
    ull acc2[4] = {0ull, 0ull, 0ull, 0ull};
    accum<CH0, 128, 8>(S, tid, rank, Wg, s0t, ht, acc2);
    float acc[8];
#pragma unroll
    for (int q = 0; q < 4; ++q) {
      const float2 t = lohi(acc2[q]);
      acc[2 * q] = t.x;
      acc[2 * q + 1] = t.y;
    }
    const int oc = tid & 127;        // matches accum remap
    const int n0 = (tid >> 7) * 8;
    const int ng0 = rank * NP + n0;
    const float bias = bg[oc];
    float v[8];
#pragma unroll
    for (int i = 0; i < 8; ++i)
      v[i] = 1.f / (1.f + __expf(-(acc[i] + bias)));
    if (oc < Un) {  // r-part -> trh (transposed), scattered to all ranks
      const int k = key8(oc);
      const int g = ng0 >> 2;
      const float* hr = ht + oc * Nn;
      const float4 h0 = *reinterpret_cast<const float4*>(hr + ((g ^ k) << 2));
      const float4 h1 = *reinterpret_cast<const float4*>(hr + (((g + 1) ^ k) << 2));
      const float4 r0 = make_float4(v[0] * h0.x, v[1] * h0.y, v[2] * h0.z, v[3] * h0.w);
      const float4 r1 = make_float4(v[4] * h1.x, v[5] * h1.y, v[6] * h1.z, v[7] * h1.w);
#pragma unroll
      for (int r = 0; r < CLS; ++r) {
        float* base = &Sp[r]->trh[oc * Nn];
        *reinterpret_cast<float4*>(base + ((g ^ k) << 2)) = r0;
        *reinterpret_cast<float4*>(base + (((g + 1) ^ k) << 2)) = r1;
      }
    } else {  // u-part -> local ub (transposed)
      const int ou = oc - Un;
      const int ku = key8(ou);
      const int gl = n0 >> 2;
      float* ur = &S.ub[ou * NP];
      *reinterpret_cast<float4*>(ur + ((gl ^ ku) << 2)) =
          make_float4(v[0], v[1], v[2], v[3]);
      *reinterpret_cast<float4*>(ur + (((gl + 1) ^ ku) << 2)) =
          make_float4(v[4], v[5], v[6], v[7]);
    }
  }

  // ================= candidate + update =================
  cl.sync();  // trh gathered; all ranks past gate accum
  if (tid < 256) hop1cd<CH0>(S, tid);
  else           hop2cd<CH0>(S, tid - 256, rank);
  __syncthreads();
  {
    ull acc2[2] = {0ull, 0ull};
    accum<CH0, 64, 4>(S, tid, rank, Wc, s0t, S.trh, acc2);
    float acc[4];
    {
      float2 t = lohi(acc2[0]);
      acc[0] = t.x; acc[1] = t.y;
      t = lohi(acc2[1]);
      acc[2] = t.x; acc[3] = t.y;
    }
    const int oc = tid & 63;         // matches accum remap
    const int n0 = (tid >> 6) * 4;
    const int ng0 = rank * NP + n0;
    const int k = key8(oc);
    const float bias = bc[oc];
    const float4 uu = *reinterpret_cast<const float4*>(
        &S.ub[oc * NP] + (((n0 >> 2) ^ k) << 2));
    const int go = ((ng0 >> 2) ^ k) << 2;
    const float4 hh = *reinterpret_cast<const float4*>(ht + oc * Nn + go);
    float4 hn;
    hn.x = uu.x * hh.x + (1.f - uu.x) * tanhf(acc[0] + bias);
    hn.y = uu.y * hh.y + (1.f - uu.y) * tanhf(acc[1] + bias);
    hn.z = uu.z * hh.z + (1.f - uu.z) * tanhf(acc[2] + bias);
    hn.w = uu.w * hh.w + (1.f - uu.w) * tanhf(acc[3] + bias);
#pragma unroll
    for (int r = 0; r < CLS; ++r) {
      float* hp = reinterpret_cast<float*>((char*)Sp[r] + hoff);
      *reinterpret_cast<float4*>(hp + oc * Nn + go) = hn;
    }
  }
}

}  // namespace

__global__ void __launch_bounds__(NT, 1) __cluster_dims__(CLS, 1, 1)
dcgru_kernel(
    const float* __restrict__ x_all,   // (B,T,N,DIN)
    const int* __restrict__ seq_len,   // (B)
    const float* __restrict__ support, // (N,N)
    const float* __restrict__ W0g, const float* __restrict__ b0g,
    const float* __restrict__ W0c, const float* __restrict__ b0c,
    const float* __restrict__ W1g, const float* __restrict__ b1g,
    const float* __restrict__ W1c, const float* __restrict__ b1c,
    const float* __restrict__ Wfc, const float* __restrict__ bfc,
    float* __restrict__ out) {         // (B,C)
  extern __shared__ float smraw[];
  Smem& S = *reinterpret_cast<Smem*>(smraw);
  cgx::cluster_group cl = cgx::this_cluster();
  const int rank = cl.block_rank();
  const int b = blockIdx.x / CLS;
  const int tid = threadIdx.x;

  Smem* Sp[CLS];
#pragma unroll
  for (int r = 0; r < CLS; ++r)
    Sp[r] = reinterpret_cast<Smem*>(cl.map_shared_rank(&S, r));

  // Load own 32 rows of support.
  for (int i = tid; i < NP * Nn; i += NT)
    S.P[i] = support[rank * NP * Nn + i];
  __syncthreads();

  // Precompute P2 = (own rows of) support^2. thread = (node, 8 k-values).
  {
    const int n = tid >> 4;
    const int k8 = (tid & 15) * 8;
    const float* Pr = &S.P[n * Nn];
    float acc[8] = {0.f, 0.f, 0.f, 0.f, 0.f, 0.f, 0.f, 0.f};
    for (int m = 0; m < Nn; ++m) {
      const float p = Pr[m];
      const float4 sa = *reinterpret_cast<const float4*>(
          support + (size_t)m * Nn + k8);
      const float4 sb = *reinterpret_cast<const float4*>(
          support + (size_t)m * Nn + k8 + 4);
      acc[0] = fmaf(p, sa.x, acc[0]); acc[1] = fmaf(p, sa.y, acc[1]);
      acc[2] = fmaf(p, sa.z, acc[2]); acc[3] = fmaf(p, sa.w, acc[3]);
      acc[4] = fmaf(p, sb.x, acc[4]); acc[5] = fmaf(p, sb.y, acc[5]);
      acc[6] = fmaf(p, sb.z, acc[6]); acc[7] = fmaf(p, sb.w, acc[7]);
    }
#pragma unroll
    for (int j = 0; j < 8; ++j) S.P2[n * Nn + k8 + j] = acc[j];
  }

  // Zero transposed hidden states.
  for (int i = tid; i < Un * Nn; i += NT) {
    S.th0[i] = 0.f;
    S.th1[i] = 0.f;
  }

  const int tlast = seq_len[b] - 1;  // uniform across the cluster

  for (int t = 0; t <= tlast; ++t) {
    // stage current frame TRANSPOSED: tx[c][n] (swizzled)
    const float4 xv = reinterpret_cast<const float4*>(
        x_all + ((size_t)b * Tn + t) * (Nn * DINn))[tid];
    {
      const int n = tid >> 2;
      const int c0 = (tid & 3) * 4;
      const int k = tid & 3;  // key8(c0+j) for all j<4
      const int base = ((n >> 2) ^ k) * 4 + (n & 3);
      S.tx[(c0 + 0) * Nn + base] = xv.x;
      S.tx[(c0 + 1) * Nn + base] = xv.y;
      S.tx[(c0 + 2) * Nn + base] = xv.z;
      S.tx[(c0 + 3) * Nn + base] = xv.w;
    }
    cell<DINn>(cl, S, Sp, tid, rank, S.tx, S.th0, W0g, b0g, W0c, b0c);
    cell<Un>(cl, S, Sp, tid, rank, S.th0, S.th1, W1g, b1g, W1c, b1c);
  }

  cl.sync();  // all th1 scatters visible in rank 0's copy

  if (rank == 0) {
    // classifier: max_n( relu(h1[n]) @ Wfc + bfc ); t1 is dead, use as scratch
    const int n = tid >> 2;
    const int c = tid & 3;
    float a = 0.f;
#pragma unroll 8
    for (int u = 0; u < Un; ++u) {
      const float hv = S.th1[u * Nn + (((n >> 2) ^ key8(u)) << 2) + (n & 3)];
      a = fmaf(fmaxf(hv, 0.f), Wfc[u * Cn + c], a);
    }
    S.t1[n * Cn + c] = a + bfc[c];
    __syncthreads();
    if (tid < Cn) {
      float m = S.t1[tid];
      for (int n2 = 1; n2 < Nn; ++n2) m = fmaxf(m, S.t1[n2 * Cn + tid]);
      out[b * Cn + tid] = m;
    }
  }
}

extern "C" void kernel_launch(void* const* d_in, const int* in_sizes, int n_in,
                              void* d_out, int out_size) {
  const float* x   = (const float*)d_in[0];
  const int*   sl  = (const int*)d_in[1];
  const float* sup = (const float*)d_in[2];
  const float* W0g = (const float*)d_in[3];
  const float* b0g = (const float*)d_in[4];
  const float* W0c = (const float*)d_in[5];
  const float* b0c = (const float*)d_in[6];
  const float* W1g = (const float*)d_in[7];
  const float* b1g = (const float*)d_in[8];
  const float* W1c = (const float*)d_in[9];
  const float* b1c = (const float*)d_in[10];
  const float* Wfc = (const float*)d_in[11];
  const float* bfc = (const float*)d_in[12];
  float* out = (float*)d_out;

  const size_t smem = sizeof(Smem);
  cudaFuncSetAttribute(dcgru_kernel,
                       cudaFuncAttributeMaxDynamicSharedMemorySize, (int)smem);
  dcgru_kernel<<<Bn * CLS, NT, smem>>>(x, sl, sup, W0g, b0g, W0c, b0c,
                                       W1g, b1g, W1c, b1c, Wfc, bfc, out);
}

// round 17
// speedup vs baseline: 1.7071x; 1.0129x over previous
#include <cuda_runtime.h>
#include <cooperative_groups.h>
#include <math.h>

namespace cgx = cooperative_groups;
#define DEVINL __device__ __forceinline__

namespace {

constexpr int Bn   = 32;   // batch
constexpr int Tn   = 256;  // timesteps
constexpr int Nn   = 128;  // nodes
constexpr int DINn = 16;   // input features
constexpr int Un   = 64;   // hidden units
constexpr int Cn   = 4;    // classes
constexpr int CLS  = 4;    // cluster size (CTAs per batch)
constexpr int NP   = 32;   // nodes owned per CTA
constexpr int NT   = 512;  // threads per CTA

typedef unsigned long long ull;

// packed fp32x2 FMA (sm_103a): d.lo += a.lo*b.lo; d.hi += a.hi*b.hi (exact fp32)
DEVINL void fma2(ull& d, ull a, ull b) {
  asm("fma.rn.f32x2 %0, %1, %2, %0;" : "+l"(d) : "l"(a), "l"(b));
}
DEVINL ull dup2(float a) {
  ull r; asm("mov.b64 %0, {%1, %1};" : "=l"(r) : "f"(a)); return r;
}
DEVINL float2 lohi(ull v) {
  float2 r; asm("mov.b64 {%0, %1}, %2;" : "=f"(r.x), "=f"(r.y) : "l"(v)); return r;
}
DEVINL float rsum(ull v) { const float2 t = lohi(v); return t.x + t.y; }

// branch-free fast sigmoid / tanh (MUFU-based, ~1e-6 accurate; tolerance 1e-3)
DEVINL float fsigmoid(float x) {
  return __fdividef(1.f, 1.f + __expf(-x));
}
DEVINL float ftanh(float x) {
  const float t = __expf(-2.f * fabsf(x));
  const float m = __fdividef(1.f - t, 1.f + t);
  return copysignf(m, x);
}

// Activation buffers TRANSPOSED: t[c][n], 3-bit XOR swizzle on float4 granules.
struct Smem {
  float P[NP * Nn];     // own 32 rows of support           (16 KB)
  float P2[NP * Nn];    // own 32 rows of support^2         (16 KB)
  float tx[DINn * Nn];  // transposed input frame           ( 8 KB)
  float th0[Un * Nn];   // transposed hidden, layer 0       (32 KB)
  float th1[Un * Nn];   // transposed hidden, layer 1       (32 KB)
  float trh[Un * Nn];   // transposed r*h                   (32 KB)
  float t1[Nn * NP];    // P z,   own nodes [c][n local]    (16 KB)
  float t2[Nn * NP];    // 2P^2z - z, own [c][n local]      (16 KB)
  float ub[Un * NP];    // update gate [u][n local]         ( 8 KB)
};                      // 45056 floats = 180224 B

DEVINL int key8(int c) { return (c >> 2) & 7; }

// row base + swizzle key for concat channel c (x-part then h-part)
template <int CH0>
DEVINL const float* zrow(const float* __restrict__ s0t,
                         const float* __restrict__ s1t, int c, int& key) {
  if (c < CH0) { key = key8(c); return s0t + c * Nn; }
  const int ch = c - CH0;
  key = key8(ch);
  return s1t + ch * Nn;
}

// ---- gate hop1 (threads 0-255): t1[c][n] = sum_k P[n][k] z[k][c], LOCAL.
template <int CH0>
DEVINL void hop1g(Smem& S, int t, const float* __restrict__ s0t,
                  const float* __restrict__ s1t) {
  constexpr int CIN = CH0 + Un;
  const int lane = t & 31;
  const int c4 = lane * 4;
  if (c4 >= CIN) return;
  const int n0 = (t >> 5) * 4;
  const float* Pr0 = &S.P[(n0 + 0) * Nn];
  const float* Pr1 = &S.P[(n0 + 1) * Nn];
  const float* Pr2 = &S.P[(n0 + 2) * Nn];
  const float* Pr3 = &S.P[(n0 + 3) * Nn];
  const float* zr[4];
  int zk[4];
#pragma unroll
  for (int j = 0; j < 4; ++j) zr[j] = zrow<CH0>(s0t, s1t, c4 + j, zk[j]);
  ull a2[4][4] = {};
#pragma unroll 4
  for (int k = 0; k < Nn; k += 4) {
    const int g = k >> 2;
    const ulonglong2 p0 = *reinterpret_cast<const ulonglong2*>(Pr0 + k);
    const ulonglong2 p1 = *reinterpret_cast<const ulonglong2*>(Pr1 + k);
    const ulonglong2 p2 = *reinterpret_cast<const ulonglong2*>(Pr2 + k);
    const ulonglong2 p3 = *reinterpret_cast<const ulonglong2*>(Pr3 + k);
#pragma unroll
    for (int j = 0; j < 4; ++j) {
      const ulonglong2 z = *reinterpret_cast<const ulonglong2*>(
          zr[j] + ((g ^ zk[j]) << 2));
      fma2(a2[0][j], p0.x, z.x); fma2(a2[0][j], p0.y, z.y);
      fma2(a2[1][j], p1.x, z.x); fma2(a2[1][j], p1.y, z.y);
      fma2(a2[2][j], p2.x, z.x); fma2(a2[2][j], p2.y, z.y);
      fma2(a2[3][j], p3.x, z.x); fma2(a2[3][j], p3.y, z.y);
    }
  }
  const int gl = n0 >> 2;
  const int tk = lane & 7;  // == key8(c4+j)
#pragma unroll
  for (int j = 0; j < 4; ++j)
    *reinterpret_cast<float4*>(&S.t1[(c4 + j) * NP + ((gl ^ tk) << 2)]) =
        make_float4(rsum(a2[0][j]), rsum(a2[1][j]),
                    rsum(a2[2][j]), rsum(a2[3][j]));
}

// ---- gate hop2 (threads 256-511): t2[c][n] = 2*sum_k P2[n][k] z[k][c] - z[n][c].
template <int CH0>
DEVINL void hop2g(Smem& S, int t, int rank, const float* __restrict__ s0t,
                  const float* __restrict__ s1t) {
  constexpr int CIN = CH0 + Un;
  const int lane = t & 31;
  const int c4 = lane * 4;
  if (c4 >= CIN) return;
  const int n0 = (t >> 5) * 4;
  const float* Pr0 = &S.P2[(n0 + 0) * Nn];
  const float* Pr1 = &S.P2[(n0 + 1) * Nn];
  const float* Pr2 = &S.P2[(n0 + 2) * Nn];
  const float* Pr3 = &S.P2[(n0 + 3) * Nn];
  const float* zr[4];
  int zk[4];
#pragma unroll
  for (int j = 0; j < 4; ++j) zr[j] = zrow<CH0>(s0t, s1t, c4 + j, zk[j]);
  ull a2[4][4] = {};
#pragma unroll 4
  for (int k = 0; k < Nn; k += 4) {
    const int g = k >> 2;
    const ulonglong2 p0 = *reinterpret_cast<const ulonglong2*>(Pr0 + k);
    const ulonglong2 p1 = *reinterpret_cast<const ulonglong2*>(Pr1 + k);
    const ulonglong2 p2 = *reinterpret_cast<const ulonglong2*>(Pr2 + k);
    const ulonglong2 p3 = *reinterpret_cast<const ulonglong2*>(Pr3 + k);
#pragma unroll
    for (int j = 0; j < 4; ++j) {
      const ulonglong2 z = *reinterpret_cast<const ulonglong2*>(
          zr[j] + ((g ^ zk[j]) << 2));
      fma2(a2[0][j], p0.x, z.x); fma2(a2[0][j], p0.y, z.y);
      fma2(a2[1][j], p1.x, z.x); fma2(a2[1][j], p1.y, z.y);
      fma2(a2[2][j], p2.x, z.x); fma2(a2[2][j], p2.y, z.y);
      fma2(a2[3][j], p3.x, z.x); fma2(a2[3][j], p3.y, z.y);
    }
  }
  const int gl = n0 >> 2;
  const int g0 = (rank * NP + n0) >> 2;
  const int tk = lane & 7;
#pragma unroll
  for (int j = 0; j < 4; ++j) {
    const float4 z0 = *reinterpret_cast<const float4*>(
        zr[j] + ((g0 ^ zk[j]) << 2));
    *reinterpret_cast<float4*>(&S.t2[(c4 + j) * NP + ((gl ^ tk) << 2)]) =
        make_float4(2.f * rsum(a2[0][j]) - z0.x, 2.f * rsum(a2[1][j]) - z0.y,
                    2.f * rsum(a2[2][j]) - z0.z, 2.f * rsum(a2[3][j]) - z0.w);
  }
}

// ---- candidate hop1 (threads 0-255): rh channels only -> t1 rows [CH0, CH0+64).
template <int CH0>
DEVINL void hop1cd(Smem& S, int t) {
  const int cn = t & 15;
  const int ch4 = cn * 4;
  const int tk = cn & 7;  // key8(ch4+j) in trh
  const int n0 = (t >> 4) * 2;
  const float* Pr0 = &S.P[(n0 + 0) * Nn];
  const float* Pr1 = &S.P[(n0 + 1) * Nn];
  const float* zr[4];
#pragma unroll
  for (int j = 0; j < 4; ++j) zr[j] = &S.trh[(ch4 + j) * Nn];
  ull a2[2][4] = {};
#pragma unroll 4
  for (int k = 0; k < Nn; k += 4) {
    const int g = (k >> 2) ^ tk;
    const ulonglong2 p0 = *reinterpret_cast<const ulonglong2*>(Pr0 + k);
    const ulonglong2 p1 = *reinterpret_cast<const ulonglong2*>(Pr1 + k);
#pragma unroll
    for (int j = 0; j < 4; ++j) {
      const ulonglong2 z = *reinterpret_cast<const ulonglong2*>(zr[j] + (g << 2));
      fma2(a2[0][j], p0.x, z.x); fma2(a2[0][j], p0.y, z.y);
      fma2(a2[1][j], p1.x, z.x); fma2(a2[1][j], p1.y, z.y);
    }
  }
  const int ksd = ((CH0 >> 2) + cn) & 7;  // key8 of destination row CH0+ch4+j
  const int gl = n0 >> 2, ofl = n0 & 3;
#pragma unroll
  for (int j = 0; j < 4; ++j)
    *reinterpret_cast<float2*>(
        &S.t1[(CH0 + ch4 + j) * NP + ((gl ^ ksd) << 2) + ofl]) =
        make_float2(rsum(a2[0][j]), rsum(a2[1][j]));
}

// ---- candidate hop2 (threads 256-511): rh channels via P2 -> t2.
template <int CH0>
DEVINL void hop2cd(Smem& S, int t, int rank) {
  const int cn = t & 15;
  const int ch4 = cn * 4;
  const int tk = cn & 7;
  const int n0 = (t >> 4) * 2;
  const float* Pr0 = &S.P2[(n0 + 0) * Nn];
  const float* Pr1 = &S.P2[(n0 + 1) * Nn];
  const float* zr[4];
#pragma unroll
  for (int j = 0; j < 4; ++j) zr[j] = &S.trh[(ch4 + j) * Nn];
  ull a2[2][4] = {};
#pragma unroll 4
  for (int k = 0; k < Nn; k += 4) {
    const int g = (k >> 2) ^ tk;
    const ulonglong2 p0 = *reinterpret_cast<const ulonglong2*>(Pr0 + k);
    const ulonglong2 p1 = *reinterpret_cast<const ulonglong2*>(Pr1 + k);
#pragma unroll
    for (int j = 0; j < 4; ++j) {
      const ulonglong2 z = *reinterpret_cast<const ulonglong2*>(zr[j] + (g << 2));
      fma2(a2[0][j], p0.x, z.x); fma2(a2[0][j], p0.y, z.y);
      fma2(a2[1][j], p1.x, z.x); fma2(a2[1][j], p1.y, z.y);
    }
  }
  const int ksd = ((CH0 >> 2) + cn) & 7;
  const int ng0 = rank * NP + n0;
  const int gw = ng0 >> 2, ofs = ng0 & 3;
  const int gl = n0 >> 2, ofl = n0 & 3;
#pragma unroll
  for (int j = 0; j < 4; ++j) {
    const float2 z0 = *reinterpret_cast<const float2*>(
        &S.trh[(ch4 + j) * Nn + ((gw ^ tk) << 2) + ofs]);
    *reinterpret_cast<float2*>(
        &S.t2[(CH0 + ch4 + j) * NP + ((gl ^ ksd) << 2) + ofl]) =
        make_float2(2.f * rsum(a2[0][j]) - z0.x, 2.f * rsum(a2[1][j]) - z0.y);
  }
}

// ---- compute one 4-channel quad with PRELOADED W registers w[12].
template <int COUT, int NPT>
DEVINL void accum_quad(Smem& S, const float* __restrict__ zbase, int c0, int q,
                       int g1, int g2, const float* __restrict__ w,
                       ull* __restrict__ acc2) {
  const int kz = q & 7;                // key8 of zbase rows 4q..4q+3
  const int kd = ((c0 >> 2) + q) & 7;  // key8 of t1/t2 rows c0+4q..
  const float* z0p = zbase + (q * 4) * Nn + ((g1 ^ kz) << 2);
  const float* t1p = &S.t1[(c0 + q * 4) * NP + ((g2 ^ kd) << 2)];
  const float* t2p = &S.t2[(c0 + q * 4) * NP + ((g2 ^ kd) << 2)];
  const float* z0q = zbase + (q * 4) * Nn + (((g1 + 1) ^ kz) << 2);
  const float* t1q = &S.t1[(c0 + q * 4) * NP + (((g2 + 1) ^ kd) << 2)];
  const float* t2q = &S.t2[(c0 + q * 4) * NP + (((g2 + 1) ^ kd) << 2)];
#pragma unroll
  for (int j = 0; j < 4; ++j) {
    const ull w0 = dup2(w[3 * j + 0]);
    const ull w1 = dup2(w[3 * j + 1]);
    const ull w2 = dup2(w[3 * j + 2]);
    const ulonglong2 z0 = *reinterpret_cast<const ulonglong2*>(z0p + j * Nn);
    const ulonglong2 z1 = *reinterpret_cast<const ulonglong2*>(t1p + j * NP);
    const ulonglong2 z2 = *reinterpret_cast<const ulonglong2*>(t2p + j * NP);
    fma2(acc2[0], z0.x, w0); fma2(acc2[0], z1.x, w1); fma2(acc2[0], z2.x, w2);
    fma2(acc2[1], z0.y, w0); fma2(acc2[1], z1.y, w1); fma2(acc2[1], z2.y, w2);
    if (NPT == 8) {
      const ulonglong2 z0b = *reinterpret_cast<const ulonglong2*>(z0q + j * Nn);
      const ulonglong2 z1b = *reinterpret_cast<const ulonglong2*>(t1q + j * NP);
      const ulonglong2 z2b = *reinterpret_cast<const ulonglong2*>(t2q + j * NP);
      fma2(acc2[2], z0b.x, w0); fma2(acc2[2], z1b.x, w1); fma2(acc2[2], z2b.x, w2);
      fma2(acc2[3], z0b.y, w0); fma2(acc2[3], z1b.y, w1); fma2(acc2[3], z2b.y, w2);
    }
  }
}

// ---- projection inner part: software-pipelined W double-buffer.
template <int COUT, int NPT, int NCH>
DEVINL void accum_part(Smem& S, const float* __restrict__ zbase, int c0,
                       const float* __restrict__ Wp0, int g1, int g2,
                       ull* __restrict__ acc2) {
  constexpr int NQ = NCH / 4;  // always even (4, 16, or 32)
  float wa[12], wb[12];
#pragma unroll
  for (int r = 0; r < 12; ++r) wa[r] = Wp0[r * COUT];
#pragma unroll 2
  for (int q = 0; q < NQ; q += 2) {
    {  // prefetch quad q+1 (always exists: NQ even)
      const float* Wn = Wp0 + (size_t)(12 * (q + 1)) * COUT;
#pragma unroll
      for (int r = 0; r < 12; ++r) wb[r] = Wn[r * COUT];
    }
    accum_quad<COUT, NPT>(S, zbase, c0, q, g1, g2, wa, acc2);
    if (q + 2 < NQ) {  // prefetch quad q+2 (predicated off on last iter)
      const float* Wn = Wp0 + (size_t)(12 * (q + 2)) * COUT;
#pragma unroll
      for (int r = 0; r < 12; ++r) wa[r] = Wn[r * COUT];
    }
    accum_quad<COUT, NPT>(S, zbase, c0, q + 1, g1, g2, wb, acc2);
  }
}

// ---- projection: oc = tid & (COUT-1) -> coalesced W; z loads broadcast.
template <int CH0, int COUT, int NPT>
DEVINL void accum(Smem& S, int tid, int rank, const float* __restrict__ W,
                  const float* __restrict__ s0t, const float* __restrict__ s1t,
                  ull* __restrict__ acc2) {
  const int oc = tid & (COUT - 1);
  const int n0 = (tid / COUT) * NPT;
  const int g1 = (rank * NP + n0) >> 2;  // global granule (replicated z0)
  const int g2 = n0 >> 2;                // local granule (t1, t2)
  accum_part<COUT, NPT, CH0>(S, s0t, 0, W + oc, g1, g2, acc2);
  accum_part<COUT, NPT, Un>(S, s1t, CH0,
                            W + (size_t)(3 * CH0) * COUT + oc, g1, g2, acc2);
}

// ---- one DCGRU cell, cluster-cooperative; ht = this layer's transposed h.
template <int CH0>
DEVINL void cell(cgx::cluster_group& cl, Smem& S, Smem* const* Sp, int tid,
                 int rank, const float* __restrict__ s0t, float* __restrict__ ht,
                 const float* __restrict__ Wg, const float* __restrict__ bg,
                 const float* __restrict__ Wc, const float* __restrict__ bc) {
  const size_t hoff = (size_t)((const char*)ht - (const char*)&S);

  // ================= gate =================
  cl.sync();  // replicated inputs (h / trh / h-scatters) visible everywhere
  if (tid < 256) hop1g<CH0>(S, tid, s0t, ht);
  else           hop2g<CH0>(S, tid - 256, rank, s0t, ht);
  __syncthreads();
  {
    ull acc2[4] = {0ull, 0ull, 0ull, 0ull};
    accum<CH0, 128, 8>(S, tid, rank, Wg, s0t, ht, acc2);
    float acc[8];
#pragma unroll
    for (int q = 0; q < 4; ++q) {
      const float2 t = lohi(acc2[q]);
      acc[2 * q] = t.x;
      acc[2 * q + 1] = t.y;
    }
    const int oc = tid & 127;        // matches accum remap
    const int n0 = (tid >> 7) * 8;
    const int ng0 = rank * NP + n0;
    const float bias = bg[oc];
    float v[8];
#pragma unroll
    for (int i = 0; i < 8; ++i)
      v[i] = fsigmoid(acc[i] + bias);
    if (oc < Un) {  // r-part -> trh (transposed), scattered to all ranks
      const int k = key8(oc);
      const int g = ng0 >> 2;
      const float* hr = ht + oc * Nn;
      const float4 h0 = *reinterpret_cast<const float4*>(hr + ((g ^ k) << 2));
      const float4 h1 = *reinterpret_cast<const float4*>(hr + (((g + 1) ^ k) << 2));
      const float4 r0 = make_float4(v[0] * h0.x, v[1] * h0.y, v[2] * h0.z, v[3] * h0.w);
      const float4 r1 = make_float4(v[4] * h1.x, v[5] * h1.y, v[6] * h1.z, v[7] * h1.w);
#pragma unroll
      for (int r = 0; r < CLS; ++r) {
        float* base = &Sp[r]->trh[oc * Nn];
        *reinterpret_cast<float4*>(base + ((g ^ k) << 2)) = r0;
        *reinterpret_cast<float4*>(base + (((g + 1) ^ k) << 2)) = r1;
      }
    } else {  // u-part -> local ub (transposed)
      const int ou = oc - Un;
      const int ku = key8(ou);
      const int gl = n0 >> 2;
      float* ur = &S.ub[ou * NP];
      *reinterpret_cast<float4*>(ur + ((gl ^ ku) << 2)) =
          make_float4(v[0], v[1], v[2], v[3]);
      *reinterpret_cast<float4*>(ur + (((gl + 1) ^ ku) << 2)) =
          make_float4(v[4], v[5], v[6], v[7]);
    }
  }

  // ================= candidate + update =================
  cl.sync();  // trh gathered; all ranks past gate accum
  if (tid < 256) hop1cd<CH0>(S, tid);
  else           hop2cd<CH0>(S, tid - 256, rank);
  __syncthreads();
  {
    ull acc2[2] = {0ull, 0ull};
    accum<CH0, 64, 4>(S, tid, rank, Wc, s0t, S.trh, acc2);
    float acc[4];
    {
      float2 t = lohi(acc2[0]);
      acc[0] = t.x; acc[1] = t.y;
      t = lohi(acc2[1]);
      acc[2] = t.x; acc[3] = t.y;
    }
    const int oc = tid & 63;         // matches accum remap
    const int n0 = (tid >> 6) * 4;
    const int ng0 = rank * NP + n0;
    const int k = key8(oc);
    const float bias = bc[oc];
    const float4 uu = *reinterpret_cast<const float4*>(
        &S.ub[oc * NP] + (((n0 >> 2) ^ k) << 2));
    const int go = ((ng0 >> 2) ^ k) << 2;
    const float4 hh = *reinterpret_cast<const float4*>(ht + oc * Nn + go);
    float4 hn;
    hn.x = uu.x * hh.x + (1.f - uu.x) * ftanh(acc[0] + bias);
    hn.y = uu.y * hh.y + (1.f - uu.y) * ftanh(acc[1] + bias);
    hn.z = uu.z * hh.z + (1.f - uu.z) * ftanh(acc[2] + bias);
    hn.w = uu.w * hh.w + (1.f - uu.w) * ftanh(acc[3] + bias);
#pragma unroll
    for (int r = 0; r < CLS; ++r) {
      float* hp = reinterpret_cast<float*>((char*)Sp[r] + hoff);
      *reinterpret_cast<float4*>(hp + oc * Nn + go) = hn;
    }
  }
}

}  // namespace

__global__ void __launch_bounds__(NT, 1) __cluster_dims__(CLS, 1, 1)
dcgru_kernel(
    const float* __restrict__ x_all,   // (B,T,N,DIN)
    const int* __restrict__ seq_len,   // (B)
    const float* __restrict__ support, // (N,N)
    const float* __restrict__ W0g, const float* __restrict__ b0g,
    const float* __restrict__ W0c, const float* __restrict__ b0c,
    const float* __restrict__ W1g, const float* __restrict__ b1g,
    const float* __restrict__ W1c, const float* __restrict__ b1c,
    const float* __restrict__ Wfc, const float* __restrict__ bfc,
    float* __restrict__ out) {         // (B,C)
  extern __shared__ float smraw[];
  Smem& S = *reinterpret_cast<Smem*>(smraw);
  cgx::cluster_group cl = cgx::this_cluster();
  const int rank = cl.block_rank();
  const int b = blockIdx.x / CLS;
  const int tid = threadIdx.x;

  Smem* Sp[CLS];
#pragma unroll
  for (int r = 0; r < CLS; ++r)
    Sp[r] = reinterpret_cast<Smem*>(cl.map_shared_rank(&S, r));

  // Load own 32 rows of support.
  for (int i = tid; i < NP * Nn; i += NT)
    S.P[i] = support[rank * NP * Nn + i];
  __syncthreads();

  // Precompute P2 = (own rows of) support^2. thread = (node, 8 k-values).
  {
    const int n = tid >> 4;
    const int k8 = (tid & 15) * 8;
    const float* Pr = &S.P[n * Nn];
    float acc[8] = {0.f, 0.f, 0.f, 0.f, 0.f, 0.f, 0.f, 0.f};
    for (int m = 0; m < Nn; ++m) {
      const float p = Pr[m];
      const float4 sa = *reinterpret_cast<const float4*>(
          support + (size_t)m * Nn + k8);
      const float4 sb = *reinterpret_cast<const float4*>(
          support + (size_t)m * Nn + k8 + 4);
      acc[0] = fmaf(p, sa.x, acc[0]); acc[1] = fmaf(p, sa.y, acc[1]);
      acc[2] = fmaf(p, sa.z, acc[2]); acc[3] = fmaf(p, sa.w, acc[3]);
      acc[4] = fmaf(p, sb.x, acc[4]); acc[5] = fmaf(p, sb.y, acc[5]);
      acc[6] = fmaf(p, sb.z, acc[6]); acc[7] = fmaf(p, sb.w, acc[7]);
    }
#pragma unroll
    for (int j = 0; j < 8; ++j) S.P2[n * Nn + k8 + j] = acc[j];
  }

  // Zero transposed hidden states.
  for (int i = tid; i < Un * Nn; i += NT) {
    S.th0[i] = 0.f;
    S.th1[i] = 0.f;
  }

  const int tlast = seq_len[b] - 1;  // uniform across the cluster

  for (int t = 0; t <= tlast; ++t) {
    // stage current frame TRANSPOSED: tx[c][n] (swizzled)
    const float4 xv = reinterpret_cast<const float4*>(
        x_all + ((size_t)b * Tn + t) * (Nn * DINn))[tid];
    {
      const int n = tid >> 2;
      const int c0 = (tid & 3) * 4;
      const int k = tid & 3;  // key8(c0+j) for all j<4
      const int base = ((n >> 2) ^ k) * 4 + (n & 3);
      S.tx[(c0 + 0) * Nn + base] = xv.x;
      S.tx[(c0 + 1) * Nn + base] = xv.y;
      S.tx[(c0 + 2) * Nn + base] = xv.z;
      S.tx[(c0 + 3) * Nn + base] = xv.w;
    }
    cell<DINn>(cl, S, Sp, tid, rank, S.tx, S.th0, W0g, b0g, W0c, b0c);
    cell<Un>(cl, S, Sp, tid, rank, S.th0, S.th1, W1g, b1g, W1c, b1c);
  }

  cl.sync();  // all th1 scatters visible in rank 0's copy

  if (rank == 0) {
    // classifier: max_n( relu(h1[n]) @ Wfc + bfc ); t1 is dead, use as scratch
    const int n = tid >> 2;
    const int c = tid & 3;
    float a = 0.f;
#pragma unroll 8
    for (int u = 0; u < Un; ++u) {
      const float hv = S.th1[u * Nn + (((n >> 2) ^ key8(u)) << 2) + (n & 3)];
      a = fmaf(fmaxf(hv, 0.f), Wfc[u * Cn + c], a);
    }
    S.t1[n * Cn + c] = a + bfc[c];
    __syncthreads();
    if (tid < Cn) {
      float m = S.t1[tid];
      for (int n2 = 1; n2 < Nn; ++n2) m = fmaxf(m, S.t1[n2 * Cn + tid]);
      out[b * Cn + tid] = m;
    }
  }
}

extern "C" void kernel_launch(void* const* d_in, const int* in_sizes, int n_in,
                              void* d_out, int out_size) {
  const float* x   = (const float*)d_in[0];
  const int*   sl  = (const int*)d_in[1];
  const float* sup = (const float*)d_in[2];
  const float* W0g = (const float*)d_in[3];
  const float* b0g = (const float*)d_in[4];
  const float* W0c = (const float*)d_in[5];
  const float* b0c = (const float*)d_in[6];
  const float* W1g = (const float*)d_in[7];
  const float* b1g = (const float*)d_in[8];
  const float* W1c = (const float*)d_in[9];
  const float* b1c = (const float*)d_in[10];
  const float* Wfc = (const float*)d_in[11];
  const float* bfc = (const float*)d_in[12];
  float* out = (float*)d_out;

  const size_t smem = sizeof(Smem);
  cudaFuncSetAttribute(dcgru_kernel,
                       cudaFuncAttributeMaxDynamicSharedMemorySize, (int)smem);
  dcgru_kernel<<<Bn * CLS, NT, smem>>>(x, sl, sup, W0g, b0g, W0c, b0c,
                                       W1g, b1g, W1c, b1c, Wfc, bfc, out);
}